// round 12
// baseline (speedup 1.0000x reference)
#include <cuda_runtime.h>
#include <cuda_fp16.h>
#include <math.h>
#include <stdint.h>

typedef unsigned long long u64;

#define CN 64
#define IN_N 64
#define RN 36
#define LN 40
#define DN 1024
#define SN 256
#define NT 512

#define DC3 32
#define NCH3 (DN/DC3)
#define DC1 64
#define NCH1 (DN/DC1)
#define SP1 68     // phase-1 staging stride (floats)
#define ST3 36     // phase-3 img/cap stride (floats)
#define WTH 40     // WT tile stride (halves)
#define ATH 40     // A (sim) tile stride (halves)

// ---- smem float offsets ----
#define OFF_WT0   0            // 256x40 halves = 5120 floats
#define OFF_WT1   5120
#define OFF_IMG0  10240        // 36x36
#define OFF_IMG1  11536
#define OFF_CAP0  12832        // 40x36
#define OFF_CAP1  14272
#define OFF_A     15712        // 48x40 halves = 960 floats (single)
#define OFF_AT    16672        // 40x40
#define OFF_INV   18272        // 48
#define OFF_RED   18320        // 48x16
#define OFF_B     19088        // 256
#define SMEM_FLOATS 19344      // 77376 B -> 2 CTAs/SM (RF-bound anyway)
// unions (time-disjoint):
#define P1_IMG0   0            // 36x68
#define P1_IMG1   2448
#define P1_CAP0   4896         // 40x68
#define P1_CAP1   7616         // ends 10336 (WT+IMG0 region, free in phase 1)
#define OFF_ATTN  10240        // 36x41 (IMG region, consumed pre-prologue)
#define OFF_GRAM  12832        // 36x37 (CAP region, consumed pre-prologue)

__device__ float  g_gram[IN_N * RN * RN];
__device__ __half g_WT[SN * DN];   // W^T [s][d], fp16

// ---------------- PTX helpers ----------------
#define FMA2(d, a, b, c) \
    asm("fma.rn.f32x2 %0, %1, %2, %3;" : "=l"(d) : "l"(a), "l"(b), "l"(c))
#define UNPK(lo, hi, v) \
    asm("mov.b64 {%0, %1}, %2;" : "=f"(lo), "=f"(hi) : "l"(v))
#define MMA_F16(d, a, b) \
    asm volatile("mma.sync.aligned.m16n8k16.row.col.f32.f16.f16.f32 " \
        "{%0,%1,%2,%3}, {%4,%5,%6,%7}, {%8,%9}, {%0,%1,%2,%3};" \
        : "+f"((d)[0]), "+f"((d)[1]), "+f"((d)[2]), "+f"((d)[3]) \
        : "r"((a)[0]), "r"((a)[1]), "r"((a)[2]), "r"((a)[3]), \
          "r"((b)[0]), "r"((b)[1]))
#define CP16(saddr, gptr) \
    asm volatile("cp.async.cg.shared.global [%0], [%1], 16;" \
                 :: "r"(saddr), "l"(gptr) : "memory")
#define CP_COMMIT() asm volatile("cp.async.commit_group;" ::: "memory")
#define CP_WAIT0()  asm volatile("cp.async.wait_group 0;" ::: "memory")

__device__ __forceinline__ uint32_t smem_u32(const void* p) {
    uint32_t a;
    asm("{ .reg .u64 t; cvta.to.shared.u64 t, %1; cvt.u32.u64 %0, t; }"
        : "=r"(a) : "l"(p));
    return a;
}
__device__ __forceinline__ float warp_sum(float v) {
    #pragma unroll
    for (int o = 16; o > 0; o >>= 1) v += __shfl_xor_sync(0xffffffffu, v, o);
    return v;
}

// ---- one-time prep kernels ----
__global__ __launch_bounds__(256)
void gram_kernel(const float* __restrict__ img_g)
{
    const int i    = blockIdx.x;
    const int widx = blockIdx.y * 8 + (threadIdx.x >> 5);
    const int lane = threadIdx.x & 31;
    const int r  = widx / RN;
    const int r2 = widx - r * RN;
    const float* A = img_g + ((size_t)i * RN + r ) * DN;
    const float* B = img_g + ((size_t)i * RN + r2) * DN;
    float s = 0.f;
    #pragma unroll 8
    for (int q = lane; q < DN; q += 32)
        s = fmaf(__ldg(A + q), __ldg(B + q), s);
    s = warp_sum(s);
    if (lane == 0) g_gram[i * RN * RN + widx] = s;
}

__global__ __launch_bounds__(256)
void wtrans_kernel(const float* __restrict__ W)
{
    int idx = blockIdx.x * 256 + threadIdx.x;
    if (idx < DN * SN) {
        int d = idx >> 8, s = idx & 255;
        g_WT[s * DN + d] = __float2half(W[idx]);
    }
}

// ---------------- main fused kernel ----------------
__global__ __launch_bounds__(NT, 2)
void graphembt_kernel(const float* __restrict__ img_g,
                      const float* __restrict__ cap_g,
                      const int*   __restrict__ lens_g,
                      const float* __restrict__ b_g,
                      float*       __restrict__ out_g)
{
    extern __shared__ float sm[];
    const int i    = blockIdx.x;
    const int c    = blockIdx.y;
    const int tid  = threadIdx.x;
    const int w    = tid >> 5;       // 0..15
    const int lane = tid & 31;
    const int gq   = lane >> 2;
    const int tg   = lane & 3;

    const uint32_t sb = smem_u32(sm);

    const float* imgB = img_g + (size_t)i * (RN * DN);
    const float* capB = cap_g + (size_t)c * (LN * DN);

    if (tid < SN / 4)
        *(float4*)(sm + OFF_B + tid * 4) = *(const float4*)(b_g + tid * 4);

    // ======== Phase 1: attn[r][l], cp.async double-buffered 64-d chunks ====
    // 480 threads: 3r x 1l register tiles
    const int rg1 = tid / 40, lg1 = tid - (tid / 40) * 40;
    const int r0 = 3 * rg1, l0 = lg1;
    u64 p2[3];
    p2[0] = 0ull; p2[1] = 0ull; p2[2] = 0ull;

    for (int idx = tid; idx < RN * (DC1 / 4); idx += NT) {
        int r = idx >> 4, d4 = idx & 15;
        CP16(sb + (P1_IMG0 + r * SP1 + d4 * 4) * 4, imgB + r * DN + d4 * 4);
    }
    for (int idx = tid; idx < LN * (DC1 / 4); idx += NT) {
        int l = idx >> 4, d4 = idx & 15;
        CP16(sb + (P1_CAP0 + l * SP1 + d4 * 4) * 4, capB + l * DN + d4 * 4);
    }
    CP_COMMIT();

    for (int k = 0; k < NCH1; k++) {
        const int cur = k & 1;
        const int imgC = cur ? P1_IMG1 : P1_IMG0;
        const int capC = cur ? P1_CAP1 : P1_CAP0;
        CP_WAIT0();
        __syncthreads();
        if (k + 1 < NCH1) {
            const int imgN = cur ? P1_IMG0 : P1_IMG1;
            const int capN = cur ? P1_CAP0 : P1_CAP1;
            const int dof = (k + 1) * DC1;
            for (int idx = tid; idx < RN * (DC1 / 4); idx += NT) {
                int r = idx >> 4, d4 = idx & 15;
                CP16(sb + (imgN + r * SP1 + d4 * 4) * 4,
                     imgB + r * DN + dof + d4 * 4);
            }
            for (int idx = tid; idx < LN * (DC1 / 4); idx += NT) {
                int l = idx >> 4, d4 = idx & 15;
                CP16(sb + (capN + l * SP1 + d4 * 4) * 4,
                     capB + l * DN + dof + d4 * 4);
            }
            CP_COMMIT();
        }
        if (tid < 480) {
            #pragma unroll 2
            for (int d4 = 0; d4 < DC1; d4 += 4) {
                ulonglong2 av[3], cv;
                #pragma unroll
                for (int a = 0; a < 3; a++)
                    av[a] = *(const ulonglong2*)(sm + imgC + (r0 + a) * SP1 + d4);
                cv = *(const ulonglong2*)(sm + capC + l0 * SP1 + d4);
                #pragma unroll
                for (int a = 0; a < 3; a++) {
                    FMA2(p2[a], av[a].x, cv.x, p2[a]);
                    FMA2(p2[a], av[a].y, cv.y, p2[a]);
                }
            }
        }
    }
    __syncthreads();
    float* sAttn = sm + OFF_ATTN;
    if (tid < 480) {
        #pragma unroll
        for (int a = 0; a < 3; a++) {
            float lo, hi;
            UNPK(lo, hi, p2[a]);
            sAttn[(r0 + a) * 41 + l0] = lo + hi;
        }
    }
    __syncthreads();

    // ======== Phase 2a: leaky+l2norm(l); stage Gram concurrently ========
    float* sGrm = sm + OFF_GRAM;
    if (tid < RN) {
        float ss = 0.f;
        #pragma unroll 4
        for (int l = 0; l < LN; l++) {
            float x = sAttn[tid * 41 + l];
            x = (x > 0.f) ? x : 0.1f * x;
            sAttn[tid * 41 + l] = x;
            ss = fmaf(x, x, ss);
        }
        float inv = 1.f / (sqrtf(ss) + 1e-8f);
        #pragma unroll 4
        for (int l = 0; l < LN; l++) sAttn[tid * 41 + l] *= inv;
    }
    for (int idx = tid; idx < RN * RN; idx += NT) {
        int r = idx / RN, r2 = idx - (idx / RN) * RN;
        sGrm[r * 37 + r2] = g_gram[i * RN * RN + idx];
    }
    __syncthreads();

    // ======== Phase 2b: softmax over r -> sAT[l][r] ========
    float* sAT = sm + OFF_AT;
    if (tid < LN) {
        float mx = -1e30f;
        #pragma unroll 4
        for (int r = 0; r < RN; r++)
            mx = fmaxf(mx, sAttn[r * 41 + tid] * 9.0f);
        float ev[RN];
        float sum = 0.f;
        #pragma unroll 4
        for (int r = 0; r < RN; r++) {
            float e = expf(sAttn[r * 41 + tid] * 9.0f - mx);
            ev[r] = e;
            sum += e;
        }
        float inv = 1.f / sum;
        #pragma unroll 4
        for (int r = 0; r < RN; r++) sAT[tid * 40 + r] = ev[r] * inv;
    }
    __syncthreads();

    // ======== ssq via Gram: ||wc_l||^2 = a^T G a  (16 warps) ========
    float* sInv = sm + OFF_INV;
    {
        const int lcnt = (w < 8) ? 3 : 2;
        for (int q = 0; q < lcnt; q++) {
            const int l = w + 16 * q;
            float t = 0.f, t2 = 0.f;
            #pragma unroll 4
            for (int rp = 0; rp < RN; rp++) {
                float a = sAT[l * 40 + rp];
                t = fmaf(sGrm[lane * 37 + rp], a, t);
                if (lane < 4)
                    t2 = fmaf(sGrm[(32 + lane) * 37 + rp], a, t2);
            }
            float part = sAT[l * 40 + lane] * t;
            if (lane < 4) part += sAT[l * 40 + 32 + lane] * t2;
            float ss = warp_sum(part);
            if (lane == 0) sInv[l] = 1.f / (sqrtf(ss) + 1e-8f);
        }
    }
    __syncthreads();   // Gram/attn consumed; phase-3 buffers free

    // zero A tile (rows 40..47 must stay zero)
    for (int idx = tid; idx < 240; idx += NT) {
        float4 z = make_float4(0.f, 0.f, 0.f, 0.f);
        *(float4*)(sm + OFF_A + idx * 4) = z;
    }

    // wc row assignment: warps 0-7 -> 3 l, warps 8-15 -> 2 l
    const int lbase = (w < 8) ? 3 * w : 24 + 2 * (w - 8);
    const int lcnt3 = (w < 8) ? 3 : 2;
    float invl[3];
    #pragma unroll
    for (int ii = 0; ii < 3; ii++)
        invl[ii] = (ii < lcnt3) ? sInv[lbase + ii] : 0.f;

    // prologue: stage chunk 0
    for (int idx = tid; idx < RN * (DC3 / 4); idx += NT) {
        int r = idx >> 3, d4 = idx & 7;
        CP16(sb + (OFF_IMG0 + r * ST3 + d4 * 4) * 4, imgB + r * DN + d4 * 4);
    }
    for (int idx = tid; idx < LN * (DC3 / 4); idx += NT) {
        int l = idx >> 3, d4 = idx & 7;
        CP16(sb + (OFF_CAP0 + l * ST3 + d4 * 4) * 4, capB + l * DN + d4 * 4);
    }
    for (int idx = tid; idx < SN * 4; idx += NT) {
        int s = idx >> 2, q = idx & 3;
        CP16(sb + OFF_WT0 * 4 + s * (WTH * 2) + q * 16,
             (const char*)(g_WT + (size_t)s * DN) + q * 16);
    }
    CP_COMMIT();

    // ======== Phase 3: wc -> sim(f16) -> mma (16 warps, n=16/warp) ========
    __half* sAh = (__half*)(sm + OFF_A);
    float acc[3][2][4];
    #pragma unroll
    for (int mt = 0; mt < 3; mt++)
        #pragma unroll
        for (int j = 0; j < 2; j++)
            #pragma unroll
            for (int q = 0; q < 4; q++) acc[mt][j][q] = 0.f;

    for (int ch = 0; ch < NCH3; ch++) {
        const int cur = ch & 1;
        const int wtC  = cur ? OFF_WT1  : OFF_WT0;
        const int imgC = cur ? OFF_IMG1 : OFF_IMG0;
        const int capC = cur ? OFF_CAP1 : OFF_CAP0;

        CP_WAIT0();
        __syncthreads();

        if (ch + 1 < NCH3) {
            const int wtN  = cur ? OFF_WT0  : OFF_WT1;
            const int imgN = cur ? OFF_IMG0 : OFF_IMG1;
            const int capN = cur ? OFF_CAP0 : OFF_CAP1;
            const int dof = (ch + 1) * DC3;
            for (int idx = tid; idx < RN * (DC3 / 4); idx += NT) {
                int r = idx >> 3, d4 = idx & 7;
                CP16(sb + (imgN + r * ST3 + d4 * 4) * 4,
                     imgB + r * DN + dof + d4 * 4);
            }
            for (int idx = tid; idx < LN * (DC3 / 4); idx += NT) {
                int l = idx >> 3, d4 = idx & 7;
                CP16(sb + (capN + l * ST3 + d4 * 4) * 4,
                     capB + l * DN + dof + d4 * 4);
            }
            for (int idx = tid; idx < SN * 4; idx += NT) {
                int s = idx >> 2, q = idx & 3;
                CP16(sb + wtN * 4 + s * (WTH * 2) + q * 16,
                     (const char*)(g_WT + (size_t)s * DN + dof) + q * 16);
            }
            CP_COMMIT();
        }

        // wc: warp covers rows lbase..lbase+lcnt3-1, lane owns d = lane
        {
            float wcv[3] = {0.f, 0.f, 0.f};
            #pragma unroll 3
            for (int r = 0; r < RN; r += 4) {
                float im0 = sm[imgC + (r + 0) * ST3 + lane];
                float im1 = sm[imgC + (r + 1) * ST3 + lane];
                float im2 = sm[imgC + (r + 2) * ST3 + lane];
                float im3 = sm[imgC + (r + 3) * ST3 + lane];
                #pragma unroll
                for (int ii = 0; ii < 3; ii++) {
                    if (ii < lcnt3) {
                        float4 a4 = *(const float4*)(sAT + (lbase + ii) * 40 + r);
                        wcv[ii] = fmaf(a4.x, im0, wcv[ii]);
                        wcv[ii] = fmaf(a4.y, im1, wcv[ii]);
                        wcv[ii] = fmaf(a4.z, im2, wcv[ii]);
                        wcv[ii] = fmaf(a4.w, im3, wcv[ii]);
                    }
                }
            }
            #pragma unroll
            for (int ii = 0; ii < 3; ii++) {
                if (ii < lcnt3) {
                    const int l = lbase + ii;
                    float v = fmaf(wcv[ii], invl[ii], -sm[capC + l * ST3 + lane]);
                    sAh[l * ATH + lane] = __float2half(v * v);
                }
            }
        }
        __syncthreads();   // sim tile ready

        // GEMM: warp w -> n slice [16w, 16w+16)
        const __half* sWTh = (const __half*)(sm + wtC);
        #pragma unroll
        for (int ks = 0; ks < 2; ks++) {
            const int kb = ks * 16;
            uint32_t af[3][4];
            #pragma unroll
            for (int mt = 0; mt < 3; mt++) {
                af[mt][0] = *(const uint32_t*)(sAh + (mt * 16 + gq    ) * ATH + kb + 2 * tg    );
                af[mt][1] = *(const uint32_t*)(sAh + (mt * 16 + gq + 8) * ATH + kb + 2 * tg    );
                af[mt][2] = *(const uint32_t*)(sAh + (mt * 16 + gq    ) * ATH + kb + 2 * tg + 8);
                af[mt][3] = *(const uint32_t*)(sAh + (mt * 16 + gq + 8) * ATH + kb + 2 * tg + 8);
            }
            uint32_t bf[2][2];
            #pragma unroll
            for (int j = 0; j < 2; j++) {
                bf[j][0] = *(const uint32_t*)(sWTh + (16 * w + 8 * j + gq) * WTH + kb + 2 * tg    );
                bf[j][1] = *(const uint32_t*)(sWTh + (16 * w + 8 * j + gq) * WTH + kb + 2 * tg + 8);
            }
            #pragma unroll
            for (int mt = 0; mt < 3; mt++)
                #pragma unroll
                for (int j = 0; j < 2; j++)
                    MMA_F16(acc[mt][j], af[mt], bf[j]);
        }
    }

    // ======== Epilogue: +b, relu, per-row ssq (quad shfl), norm, store ====
    __syncthreads();
    float* sRed = sm + OFF_RED;
    #pragma unroll
    for (int mt = 0; mt < 3; mt++) {
        #pragma unroll
        for (int half = 0; half < 2; half++) {
            const int l = mt * 16 + gq + 8 * half;
            float ssq = 0.f;
            #pragma unroll
            for (int j = 0; j < 2; j++) {
                const int s = 16 * w + 8 * j + 2 * tg;
                float x0 = fmaxf(acc[mt][j][2 * half]     + sm[OFF_B + s],     0.f);
                float x1 = fmaxf(acc[mt][j][2 * half + 1] + sm[OFF_B + s + 1], 0.f);
                acc[mt][j][2 * half]     = x0;
                acc[mt][j][2 * half + 1] = x1;
                ssq = fmaf(x0, x0, ssq);
                ssq = fmaf(x1, x1, ssq);
            }
            ssq += __shfl_xor_sync(0xffffffffu, ssq, 1);
            ssq += __shfl_xor_sync(0xffffffffu, ssq, 2);
            if (tg == 0) sRed[l * 16 + w] = ssq;
        }
    }
    __syncthreads();
    const int clen = lens_g[c];
    if (tid < LN) {
        float ss = 0.f;
        #pragma unroll
        for (int q = 0; q < 16; q++) ss += sRed[tid * 16 + q];
        float inv = 1.f / (sqrtf(ss) + 1e-8f);
        sInv[tid] = (tid < clen) ? inv : 0.f;
    }
    __syncthreads();

    float* outB = out_g + (size_t)(c * IN_N + i) * (LN * SN);
    #pragma unroll
    for (int mt = 0; mt < 3; mt++) {
        #pragma unroll
        for (int half = 0; half < 2; half++) {
            const int l = mt * 16 + gq + 8 * half;
            if (l < LN) {
                float inv = sInv[l];
                #pragma unroll
                for (int j = 0; j < 2; j++) {
                    const int s = 16 * w + 8 * j + 2 * tg;
                    float2 o;
                    o.x = acc[mt][j][2 * half]     * inv;
                    o.y = acc[mt][j][2 * half + 1] * inv;
                    *(float2*)(outB + (size_t)l * SN + s) = o;
                }
            }
        }
    }
}

extern "C" void kernel_launch(void* const* d_in, const int* in_sizes, int n_in,
                              void* d_out, int out_size)
{
    const float* img  = (const float*)d_in[0];
    const float* cap  = (const float*)d_in[1];
    const int*   lens = (const int*)  d_in[2];
    const float* W    = (const float*)d_in[5];
    const float* b    = (const float*)d_in[6];
    float* out = (float*)d_out;
    (void)in_sizes; (void)n_in; (void)out_size;

    cudaFuncSetAttribute(graphembt_kernel,
                         cudaFuncAttributeMaxDynamicSharedMemorySize,
                         SMEM_FLOATS * sizeof(float));

    dim3 ggrid(IN_N, (RN * RN) / 8);
    gram_kernel<<<ggrid, 256>>>(img);
    wtrans_kernel<<<(DN * SN + 255) / 256, 256>>>(W);
    dim3 grid(IN_N, CN);
    graphembt_kernel<<<grid, NT, SMEM_FLOATS * sizeof(float)>>>(
        img, cap, lens, b, out);
}

// round 13
// speedup vs baseline: 1.4947x; 1.4947x over previous
#include <cuda_runtime.h>
#include <cuda_fp16.h>
#include <math.h>
#include <stdint.h>

typedef unsigned long long u64;

#define CN 64
#define IN_N 64
#define RN 36
#define LN 40
#define DN 1024
#define SN 256
#define NT 256

#define DC3 64
#define NCH3 (DN/DC3)      // 16 chunks
#define DC1 64
#define NCH1 (DN/DC1)
#define SP1 68             // phase-1 staging stride (floats)
#define WTH 72             // WT tile stride (halves)
#define ATH 72             // A (sim) tile stride (halves)
#define ITH 56             // imgT tile stride (halves)
#define RPAD 48            // padded r in g_imgT

// ---- smem float offsets ----
#define OFF_WT0   0            // 256x72 halves = 9216 floats
#define OFF_WT1   9216         // ends 18432
#define OFF_IT0   18432        // 64x56 halves = 1792 floats
#define OFF_IT1   20224        // ends 22016
#define OFF_A     22016        // 48x72 halves = 1728 floats
#define OFF_ATH   23744        // 48x56 halves = 1344 floats
#define OFF_AT    25088        // 40x40 fp32
#define OFF_INV   26688        // 48
#define OFF_RED   26736        // 48x8
#define OFF_B     27120        // 256
#define SMEM_FLOATS 27392      // 109568 B -> 2 CTAs/SM
// unions (time-disjoint):
#define P1_IMG0   0            // 36x68 (inside WT region)
#define P1_IMG1   2448
#define P1_CAP0   4896         // 40x68
#define P1_CAP1   7616         // ends 10336
#define OFF_ATTN  18432        // 36x41 (IT region; consumed before prologue)
#define OFF_GRAM  22016        // 36x37 (A region; consumed before A-zero)

__device__ float  g_gram[IN_N * RN * RN];
__device__ __half g_WT[SN * DN];              // W^T [s][d], fp16
__device__ __half g_imgT[IN_N * DN * RPAD];   // img^T [i][d][r48], fp16, r>=36 zero

// ---------------- PTX helpers ----------------
#define FMA2(d, a, b, c) \
    asm("fma.rn.f32x2 %0, %1, %2, %3;" : "=l"(d) : "l"(a), "l"(b), "l"(c))
#define UNPK(lo, hi, v) \
    asm("mov.b64 {%0, %1}, %2;" : "=f"(lo), "=f"(hi) : "l"(v))
#define MMA_F16(d, a, b) \
    asm volatile("mma.sync.aligned.m16n8k16.row.col.f32.f16.f16.f32 " \
        "{%0,%1,%2,%3}, {%4,%5,%6,%7}, {%8,%9}, {%0,%1,%2,%3};" \
        : "+f"((d)[0]), "+f"((d)[1]), "+f"((d)[2]), "+f"((d)[3]) \
        : "r"((a)[0]), "r"((a)[1]), "r"((a)[2]), "r"((a)[3]), \
          "r"((b)[0]), "r"((b)[1]))
#define CP16(saddr, gptr) \
    asm volatile("cp.async.cg.shared.global [%0], [%1], 16;" \
                 :: "r"(saddr), "l"(gptr) : "memory")
#define CP_COMMIT() asm volatile("cp.async.commit_group;" ::: "memory")
#define CP_WAIT0()  asm volatile("cp.async.wait_group 0;" ::: "memory")

__device__ __forceinline__ uint32_t smem_u32(const void* p) {
    uint32_t a;
    asm("{ .reg .u64 t; cvta.to.shared.u64 t, %1; cvt.u32.u64 %0, t; }"
        : "=r"(a) : "l"(p));
    return a;
}
__device__ __forceinline__ float warp_sum(float v) {
    #pragma unroll
    for (int o = 16; o > 0; o >>= 1) v += __shfl_xor_sync(0xffffffffu, v, o);
    return v;
}

// ---- one-time prep kernels ----
__global__ __launch_bounds__(256)
void gram_kernel(const float* __restrict__ img_g)
{
    const int i    = blockIdx.x;
    const int widx = blockIdx.y * 8 + (threadIdx.x >> 5);
    const int lane = threadIdx.x & 31;
    const int r  = widx / RN;
    const int r2 = widx - r * RN;
    const float* A = img_g + ((size_t)i * RN + r ) * DN;
    const float* B = img_g + ((size_t)i * RN + r2) * DN;
    float s = 0.f;
    #pragma unroll 8
    for (int q = lane; q < DN; q += 32)
        s = fmaf(__ldg(A + q), __ldg(B + q), s);
    s = warp_sum(s);
    if (lane == 0) g_gram[i * RN * RN + widx] = s;
}

__global__ __launch_bounds__(256)
void wtrans_kernel(const float* __restrict__ W)
{
    int idx = blockIdx.x * 256 + threadIdx.x;
    if (idx < DN * SN) {
        int d = idx >> 8, s = idx & 255;
        g_WT[s * DN + d] = __float2half(W[idx]);
    }
}

// img[i][r][d] -> g_imgT[i][d][r48] fp16, r 36..47 zero
__global__ __launch_bounds__(256)
void imgtrans_kernel(const float* __restrict__ img_g)
{
    __shared__ float t[64 * 37];
    const int i  = blockIdx.x;
    const int db = blockIdx.y;     // 16 blocks of 64 d
    for (int idx = threadIdx.x; idx < RN * 64; idx += 256) {
        int r = idx >> 6, dd = idx & 63;
        t[dd * 37 + r] = img_g[((size_t)i * RN + r) * DN + db * 64 + dd];
    }
    __syncthreads();
    __half* out = g_imgT + ((size_t)i * DN + db * 64) * RPAD;
    for (int idx = threadIdx.x; idx < 64 * (RPAD / 2); idx += 256) {
        int dd = idx / (RPAD / 2), rq = idx - dd * (RPAD / 2);
        int r = 2 * rq;
        float v0 = (r     < RN) ? t[dd * 37 + r]     : 0.f;
        float v1 = (r + 1 < RN) ? t[dd * 37 + r + 1] : 0.f;
        *(__half2*)(out + dd * RPAD + r) = __floats2half2_rn(v0, v1);
    }
}

// ---------------- main fused kernel ----------------
__global__ __launch_bounds__(NT, 2)
void graphembt_kernel(const float* __restrict__ img_g,
                      const float* __restrict__ cap_g,
                      const int*   __restrict__ lens_g,
                      const float* __restrict__ b_g,
                      float*       __restrict__ out_g)
{
    extern __shared__ float sm[];
    const int i    = blockIdx.x;
    const int c    = blockIdx.y;
    const int tid  = threadIdx.x;
    const int w    = tid >> 5;       // 0..7
    const int lane = tid & 31;
    const int gq   = lane >> 2;      // 0..7
    const int tg   = lane & 3;       // 0..3

    const uint32_t sb = smem_u32(sm);

    const float* imgB = img_g + (size_t)i * (RN * DN);
    const float* capB = cap_g + (size_t)c * (LN * DN);

    if (tid < SN / 4)
        *(float4*)(sm + OFF_B + tid * 4) = *(const float4*)(b_g + tid * 4);

    // ======== Phase 1: attn[r][l], cp.async double-buffered 64-d chunks ====
    const int rg1 = tid / 20, lg1 = tid - (tid / 20) * 20;
    const int r0 = 3 * rg1, l0 = 2 * lg1;
    u64 p2[3][2];
    #pragma unroll
    for (int a = 0; a < 3; a++) { p2[a][0] = 0ull; p2[a][1] = 0ull; }

    for (int idx = tid; idx < RN * (DC1 / 4); idx += NT) {
        int r = idx >> 4, d4 = idx & 15;
        CP16(sb + (P1_IMG0 + r * SP1 + d4 * 4) * 4, imgB + r * DN + d4 * 4);
    }
    for (int idx = tid; idx < LN * (DC1 / 4); idx += NT) {
        int l = idx >> 4, d4 = idx & 15;
        CP16(sb + (P1_CAP0 + l * SP1 + d4 * 4) * 4, capB + l * DN + d4 * 4);
    }
    CP_COMMIT();

    for (int k = 0; k < NCH1; k++) {
        const int cur = k & 1;
        const int imgC = cur ? P1_IMG1 : P1_IMG0;
        const int capC = cur ? P1_CAP1 : P1_CAP0;
        CP_WAIT0();
        __syncthreads();
        if (k + 1 < NCH1) {
            const int imgN = cur ? P1_IMG0 : P1_IMG1;
            const int capN = cur ? P1_CAP0 : P1_CAP1;
            const int dof = (k + 1) * DC1;
            for (int idx = tid; idx < RN * (DC1 / 4); idx += NT) {
                int r = idx >> 4, d4 = idx & 15;
                CP16(sb + (imgN + r * SP1 + d4 * 4) * 4,
                     imgB + r * DN + dof + d4 * 4);
            }
            for (int idx = tid; idx < LN * (DC1 / 4); idx += NT) {
                int l = idx >> 4, d4 = idx & 15;
                CP16(sb + (capN + l * SP1 + d4 * 4) * 4,
                     capB + l * DN + dof + d4 * 4);
            }
            CP_COMMIT();
        }
        if (tid < 240) {
            #pragma unroll 2
            for (int d4 = 0; d4 < DC1; d4 += 4) {
                ulonglong2 av[3], cv[2];
                #pragma unroll
                for (int a = 0; a < 3; a++)
                    av[a] = *(const ulonglong2*)(sm + imgC + (r0 + a) * SP1 + d4);
                #pragma unroll
                for (int b = 0; b < 2; b++)
                    cv[b] = *(const ulonglong2*)(sm + capC + (l0 + b) * SP1 + d4);
                #pragma unroll
                for (int a = 0; a < 3; a++)
                    #pragma unroll
                    for (int b = 0; b < 2; b++) {
                        FMA2(p2[a][b], av[a].x, cv[b].x, p2[a][b]);
                        FMA2(p2[a][b], av[a].y, cv[b].y, p2[a][b]);
                    }
            }
        }
    }
    __syncthreads();
    float* sAttn = sm + OFF_ATTN;
    if (tid < 240) {
        #pragma unroll
        for (int a = 0; a < 3; a++)
            #pragma unroll
            for (int b = 0; b < 2; b++) {
                float lo, hi;
                UNPK(lo, hi, p2[a][b]);
                sAttn[(r0 + a) * 41 + (l0 + b)] = lo + hi;
            }
    }
    __syncthreads();

    // ======== Phase 2a: leaky+l2norm(l); stage Gram concurrently ========
    float* sGrm = sm + OFF_GRAM;
    if (tid < RN) {
        float ss = 0.f;
        #pragma unroll 4
        for (int l = 0; l < LN; l++) {
            float x = sAttn[tid * 41 + l];
            x = (x > 0.f) ? x : 0.1f * x;
            sAttn[tid * 41 + l] = x;
            ss = fmaf(x, x, ss);
        }
        float inv = 1.f / (sqrtf(ss) + 1e-8f);
        #pragma unroll 4
        for (int l = 0; l < LN; l++) sAttn[tid * 41 + l] *= inv;
    }
    for (int idx = tid; idx < RN * RN; idx += NT) {
        int r = idx / RN, r2 = idx - (idx / RN) * RN;
        sGrm[r * 37 + r2] = g_gram[i * RN * RN + idx];
    }
    __syncthreads();

    // ======== Phase 2b: softmax over r -> sAT[l][r] (fp32) ========
    float* sAT = sm + OFF_AT;
    if (tid < LN) {
        float mx = -1e30f;
        #pragma unroll 4
        for (int r = 0; r < RN; r++)
            mx = fmaxf(mx, sAttn[r * 41 + tid] * 9.0f);
        float ev[RN];
        float sum = 0.f;
        #pragma unroll 4
        for (int r = 0; r < RN; r++) {
            float e = expf(sAttn[r * 41 + tid] * 9.0f - mx);
            ev[r] = e;
            sum += e;
        }
        float inv = 1.f / sum;
        #pragma unroll 4
        for (int r = 0; r < RN; r++) sAT[tid * 40 + r] = ev[r] * inv;
    }
    __syncthreads();

    // ======== ssq via Gram + build fp16 sATh ========
    float* sInv = sm + OFF_INV;
    #pragma unroll
    for (int q = 0; q < 5; q++) {
        const int l = w + 8 * q;
        float t = 0.f, t2 = 0.f;
        #pragma unroll 4
        for (int rp = 0; rp < RN; rp++) {
            float a = sAT[l * 40 + rp];
            t = fmaf(sGrm[lane * 37 + rp], a, t);
            if (lane < 4)
                t2 = fmaf(sGrm[(32 + lane) * 37 + rp], a, t2);
        }
        float part = sAT[l * 40 + lane] * t;
        if (lane < 4) part += sAT[l * 40 + 32 + lane] * t2;
        float ss = warp_sum(part);
        if (lane == 0) sInv[l] = 1.f / (sqrtf(ss) + 1e-8f);
    }
    // sATh[48][56] fp16: zero-padded att weights
    {
        __half* sATh = (__half*)(sm + OFF_ATH);
        for (int idx = tid; idx < 48 * (ITH / 2); idx += NT) {
            int l = idx / (ITH / 2), rq = idx - l * (ITH / 2);
            int r = 2 * rq;
            float v0 = (l < LN && r     < RN) ? sAT[l * 40 + r]     : 0.f;
            float v1 = (l < LN && r + 1 < RN) ? sAT[l * 40 + r + 1] : 0.f;
            *(__half2*)(sATh + l * ITH + r) = __floats2half2_rn(v0, v1);
        }
    }
    __syncthreads();   // Gram (A region) consumed; attn (IT region) consumed

    // zero A tile (rows 40..47 stay zero forever)
    for (int idx = tid; idx < (48 * ATH) / 8; idx += NT) {
        float4 z = make_float4(0.f, 0.f, 0.f, 0.f);
        *(float4*)(sm + OFF_A + idx * 4) = z;
    }
    // hoist per-thread inverse norms for rows gq + 8q
    float invq[5];
    #pragma unroll
    for (int q = 0; q < 5; q++) invq[q] = sInv[gq + 8 * q];

    // prologue: stage chunk 0 (WT + imgT)
    for (int idx = tid; idx < SN * 8; idx += NT) {
        int s = idx >> 3, q = idx & 7;
        CP16(sb + OFF_WT0 * 4 + s * (WTH * 2) + q * 16,
             (const char*)(g_WT + (size_t)s * DN) + q * 16);
    }
    for (int idx = tid; idx < DC3 * 6; idx += NT) {
        int d = idx / 6, q = idx - d * 6;
        CP16(sb + OFF_IT0 * 4 + d * (ITH * 2) + q * 16,
             (const char*)(g_imgT + ((size_t)i * DN + d) * RPAD) + q * 16);
    }
    CP_COMMIT();

    // ======== Phase 3: 16 chunks of 64 d: wc(mma) -> sim -> GEMM(mma) =====
    __half* sAh  = (__half*)(sm + OFF_A);
    const __half* sATh = (const __half*)(sm + OFF_ATH);
    float acc[3][4][4];
    #pragma unroll
    for (int mt = 0; mt < 3; mt++)
        #pragma unroll
        for (int j = 0; j < 4; j++)
            #pragma unroll
            for (int q = 0; q < 4; q++) acc[mt][j][q] = 0.f;

    for (int ch = 0; ch < NCH3; ch++) {
        const int cur = ch & 1;
        const int wtC = cur ? OFF_WT1 : OFF_WT0;
        const int itC = cur ? OFF_IT1 : OFF_IT0;

        CP_WAIT0();
        __syncthreads();

        if (ch + 1 < NCH3) {
            const int wtN = cur ? OFF_WT0 : OFF_WT1;
            const int itN = cur ? OFF_IT0 : OFF_IT1;
            const int dof = (ch + 1) * DC3;
            for (int idx = tid; idx < SN * 8; idx += NT) {
                int s = idx >> 3, q = idx & 7;
                CP16(sb + wtN * 4 + s * (WTH * 2) + q * 16,
                     (const char*)(g_WT + (size_t)s * DN + dof) + q * 16);
            }
            for (int idx = tid; idx < DC3 * 6; idx += NT) {
                int d = idx / 6, q = idx - d * 6;
                CP16(sb + itN * 4 + d * (ITH * 2) + q * 16,
                     (const char*)(g_imgT + ((size_t)i * DN + dof + d) * RPAD) + q * 16);
            }
            CP_COMMIT();
        }

        // cap for this thread's sim positions: rows gq+8q, d = ch*64 + 8w + 2tg
        float2 capr[5];
        {
            const float* cp = capB + ch * DC3 + 8 * w + 2 * tg;
            #pragma unroll
            for (int q = 0; q < 5; q++)
                capr[q] = *(const float2*)(cp + (size_t)(gq + 8 * q) * DN);
        }

        // wc via mma: warp w -> n-tile d_local in [8w, 8w+8), 3 m-tiles
        float wca[3][4];
        #pragma unroll
        for (int mt = 0; mt < 3; mt++)
            #pragma unroll
            for (int q = 0; q < 4; q++) wca[mt][q] = 0.f;
        const __half* sIT = (const __half*)(sm + itC);
        #pragma unroll
        for (int kt = 0; kt < 3; kt++) {
            const int kb = kt * 16;
            uint32_t bf[2];
            bf[0] = *(const uint32_t*)(sIT + (8 * w + gq) * ITH + kb + 2 * tg);
            bf[1] = *(const uint32_t*)(sIT + (8 * w + gq) * ITH + kb + 2 * tg + 8);
            #pragma unroll
            for (int mt = 0; mt < 3; mt++) {
                uint32_t af[4];
                af[0] = *(const uint32_t*)(sATh + (mt * 16 + gq    ) * ITH + kb + 2 * tg    );
                af[1] = *(const uint32_t*)(sATh + (mt * 16 + gq + 8) * ITH + kb + 2 * tg    );
                af[2] = *(const uint32_t*)(sATh + (mt * 16 + gq    ) * ITH + kb + 2 * tg + 8);
                af[3] = *(const uint32_t*)(sATh + (mt * 16 + gq + 8) * ITH + kb + 2 * tg + 8);
                MMA_F16(wca[mt], af, bf);
            }
        }
        // sim = (wc*inv - cap)^2 -> fp16 A tile
        {
            const int dl = 8 * w + 2 * tg;
            #pragma unroll
            for (int mt = 0; mt < 3; mt++) {
                const int l = mt * 16 + gq;
                float v0 = fmaf(wca[mt][0], invq[2 * mt], -capr[2 * mt].x);
                float v1 = fmaf(wca[mt][1], invq[2 * mt], -capr[2 * mt].y);
                *(__half2*)(sAh + l * ATH + dl) = __floats2half2_rn(v0 * v0, v1 * v1);
                if (mt < 2) {
                    float v2 = fmaf(wca[mt][2], invq[2 * mt + 1], -capr[2 * mt + 1].x);
                    float v3 = fmaf(wca[mt][3], invq[2 * mt + 1], -capr[2 * mt + 1].y);
                    *(__half2*)(sAh + (l + 8) * ATH + dl) =
                        __floats2half2_rn(v2 * v2, v3 * v3);
                }
            }
        }
        __syncthreads();   // sim tile ready

        // GEMM: warp w -> n slice [32w, 32w+32), k = 64
        const __half* sWTh = (const __half*)(sm + wtC);
        #pragma unroll
        for (int ks = 0; ks < 4; ks++) {
            const int kb = ks * 16;
            uint32_t af[3][4];
            #pragma unroll
            for (int mt = 0; mt < 3; mt++) {
                af[mt][0] = *(const uint32_t*)(sAh + (mt * 16 + gq    ) * ATH + kb + 2 * tg    );
                af[mt][1] = *(const uint32_t*)(sAh + (mt * 16 + gq + 8) * ATH + kb + 2 * tg    );
                af[mt][2] = *(const uint32_t*)(sAh + (mt * 16 + gq    ) * ATH + kb + 2 * tg + 8);
                af[mt][3] = *(const uint32_t*)(sAh + (mt * 16 + gq + 8) * ATH + kb + 2 * tg + 8);
            }
            uint32_t bf[4][2];
            #pragma unroll
            for (int j = 0; j < 4; j++) {
                bf[j][0] = *(const uint32_t*)(sWTh + (32 * w + 8 * j + gq) * WTH + kb + 2 * tg    );
                bf[j][1] = *(const uint32_t*)(sWTh + (32 * w + 8 * j + gq) * WTH + kb + 2 * tg + 8);
            }
            #pragma unroll
            for (int mt = 0; mt < 3; mt++)
                #pragma unroll
                for (int j = 0; j < 4; j++)
                    MMA_F16(acc[mt][j], af[mt], bf[j]);
        }
    }

    // ======== Epilogue: +b, relu, per-row ssq (quad shfl), norm, store ====
    __syncthreads();
    float* sRed = sm + OFF_RED;
    #pragma unroll
    for (int mt = 0; mt < 3; mt++) {
        #pragma unroll
        for (int half = 0; half < 2; half++) {
            const int l = mt * 16 + gq + 8 * half;
            float ssq = 0.f;
            #pragma unroll
            for (int j = 0; j < 4; j++) {
                const int s = 32 * w + 8 * j + 2 * tg;
                float x0 = fmaxf(acc[mt][j][2 * half]     + sm[OFF_B + s],     0.f);
                float x1 = fmaxf(acc[mt][j][2 * half + 1] + sm[OFF_B + s + 1], 0.f);
                acc[mt][j][2 * half]     = x0;
                acc[mt][j][2 * half + 1] = x1;
                ssq = fmaf(x0, x0, ssq);
                ssq = fmaf(x1, x1, ssq);
            }
            ssq += __shfl_xor_sync(0xffffffffu, ssq, 1);
            ssq += __shfl_xor_sync(0xffffffffu, ssq, 2);
            if (tg == 0 && l < 48) sRed[l * 8 + w] = ssq;
        }
    }
    __syncthreads();
    const int clen = lens_g[c];
    if (tid < LN) {
        float ss = 0.f;
        #pragma unroll
        for (int q = 0; q < 8; q++) ss += sRed[tid * 8 + q];
        float inv = 1.f / (sqrtf(ss) + 1e-8f);
        sInv[tid] = (tid < clen) ? inv : 0.f;
    }
    __syncthreads();

    float* outB = out_g + (size_t)(c * IN_N + i) * (LN * SN);
    #pragma unroll
    for (int mt = 0; mt < 3; mt++) {
        #pragma unroll
        for (int half = 0; half < 2; half++) {
            const int l = mt * 16 + gq + 8 * half;
            if (l < LN) {
                float inv = sInv[l];
                #pragma unroll
                for (int j = 0; j < 4; j++) {
                    const int s = 32 * w + 8 * j + 2 * tg;
                    float2 o;
                    o.x = acc[mt][j][2 * half]     * inv;
                    o.y = acc[mt][j][2 * half + 1] * inv;
                    *(float2*)(outB + (size_t)l * SN + s) = o;
                }
            }
        }
    }
}

extern "C" void kernel_launch(void* const* d_in, const int* in_sizes, int n_in,
                              void* d_out, int out_size)
{
    const float* img  = (const float*)d_in[0];
    const float* cap  = (const float*)d_in[1];
    const int*   lens = (const int*)  d_in[2];
    const float* W    = (const float*)d_in[5];
    const float* b    = (const float*)d_in[6];
    float* out = (float*)d_out;
    (void)in_sizes; (void)n_in; (void)out_size;

    cudaFuncSetAttribute(graphembt_kernel,
                         cudaFuncAttributeMaxDynamicSharedMemorySize,
                         SMEM_FLOATS * sizeof(float));

    dim3 ggrid(IN_N, (RN * RN) / 8);
    gram_kernel<<<ggrid, 256>>>(img);
    wtrans_kernel<<<(DN * SN + 255) / 256, 256>>>(W);
    dim3 tgrid(IN_N, DN / 64);
    imgtrans_kernel<<<tgrid, 256>>>(img);
    dim3 grid(IN_N, CN);
    graphembt_kernel<<<grid, NT, SMEM_FLOATS * sizeof(float)>>>(
        img, cap, lens, b, out);
}

// round 14
// speedup vs baseline: 1.5379x; 1.0289x over previous
#include <cuda_runtime.h>
#include <cuda_fp16.h>
#include <math.h>
#include <stdint.h>

typedef unsigned long long u64;

#define CN 64
#define IN_N 64
#define RN 36
#define LN 40
#define DN 1024
#define SN 256
#define NT 256

#define DC3 64
#define NCH3 (DN/DC3)      // 16 chunks
#define DC1 64
#define NCH1 (DN/DC1)
#define SP1 68             // phase-1 staging stride (floats)
#define WTH 72             // WT tile stride (halves)
#define ATH 72             // A (sim) tile stride (halves)
#define ITH 56             // imgT tile stride (halves)
#define RPAD 48            // padded r in g_imgT

// ---- smem float offsets ----
#define OFF_WT0   0            // 256x72 halves = 9216 floats
#define OFF_WT1   9216
#define OFF_IT0   18432       // 64x56 halves = 1792 floats
#define OFF_IT1   20224
#define OFF_A     22016       // 48x72 halves = 1728 floats
#define OFF_ATH   23744       // 48x56 halves = 1344 floats
#define OFF_AT    25088       // 40x40 fp32
#define OFF_INV   26688       // 48
#define OFF_RED   26736       // 48x8
#define OFF_B     27120       // 256
#define SMEM_FLOATS 27392     // 109568 B -> 2 CTAs/SM
// unions (time-disjoint):
#define P1_IMG0   0
#define P1_IMG1   2448
#define P1_CAP0   4896
#define P1_CAP1   7616
#define OFF_ATTN  18432
#define OFF_GRAM  22016

__device__ float  g_gram[IN_N * RN * RN];
__device__ __half g_WT[SN * DN];
__device__ __half g_imgT[IN_N * DN * RPAD];

// ---------------- PTX helpers ----------------
#define FMA2(d, a, b, c) \
    asm("fma.rn.f32x2 %0, %1, %2, %3;" : "=l"(d) : "l"(a), "l"(b), "l"(c))
#define UNPK(lo, hi, v) \
    asm("mov.b64 {%0, %1}, %2;" : "=f"(lo), "=f"(hi) : "l"(v))
#define MMA_F16(d, a, b) \
    asm volatile("mma.sync.aligned.m16n8k16.row.col.f32.f16.f16.f32 " \
        "{%0,%1,%2,%3}, {%4,%5,%6,%7}, {%8,%9}, {%0,%1,%2,%3};" \
        : "+f"((d)[0]), "+f"((d)[1]), "+f"((d)[2]), "+f"((d)[3]) \
        : "r"((a)[0]), "r"((a)[1]), "r"((a)[2]), "r"((a)[3]), \
          "r"((b)[0]), "r"((b)[1]))
#define CP16(saddr, gptr) \
    asm volatile("cp.async.cg.shared.global [%0], [%1], 16;" \
                 :: "r"(saddr), "l"(gptr) : "memory")
#define CP_COMMIT() asm volatile("cp.async.commit_group;" ::: "memory")
#define CP_WAIT0()  asm volatile("cp.async.wait_group 0;" ::: "memory")
#define LDSM_X4(R0, R1, R2, R3, ADDR) \
    asm volatile("ldmatrix.sync.aligned.m8n8.x4.shared.b16 {%0,%1,%2,%3}, [%4];" \
        : "=r"(R0), "=r"(R1), "=r"(R2), "=r"(R3) : "r"(ADDR))
#define LDSM_X2(R0, R1, ADDR) \
    asm volatile("ldmatrix.sync.aligned.m8n8.x2.shared.b16 {%0,%1}, [%2];" \
        : "=r"(R0), "=r"(R1) : "r"(ADDR))
#define STSM_X2(ADDR, R0, R1) \
    asm volatile("stmatrix.sync.aligned.m8n8.x2.shared.b16 [%0], {%1,%2};" \
        :: "r"(ADDR), "r"(R0), "r"(R1) : "memory")
#define STSM_X1(ADDR, R0) \
    asm volatile("stmatrix.sync.aligned.m8n8.x1.shared.b16 [%0], {%1};" \
        :: "r"(ADDR), "r"(R0) : "memory")

__device__ __forceinline__ uint32_t smem_u32(const void* p) {
    uint32_t a;
    asm("{ .reg .u64 t; cvta.to.shared.u64 t, %1; cvt.u32.u64 %0, t; }"
        : "=r"(a) : "l"(p));
    return a;
}
__device__ __forceinline__ float warp_sum(float v) {
    #pragma unroll
    for (int o = 16; o > 0; o >>= 1) v += __shfl_xor_sync(0xffffffffu, v, o);
    return v;
}
__device__ __forceinline__ uint32_t h2u(float a, float b) {
    __half2 h = __floats2half2_rn(a, b);
    return *(uint32_t*)&h;
}

// ---- one-time prep kernels ----
__global__ __launch_bounds__(256)
void gram_kernel(const float* __restrict__ img_g)
{
    const int i    = blockIdx.x;
    const int widx = blockIdx.y * 8 + (threadIdx.x >> 5);
    const int lane = threadIdx.x & 31;
    const int r  = widx / RN;
    const int r2 = widx - r * RN;
    const float* A = img_g + ((size_t)i * RN + r ) * DN;
    const float* B = img_g + ((size_t)i * RN + r2) * DN;
    float s = 0.f;
    #pragma unroll 8
    for (int q = lane; q < DN; q += 32)
        s = fmaf(__ldg(A + q), __ldg(B + q), s);
    s = warp_sum(s);
    if (lane == 0) g_gram[i * RN * RN + widx] = s;
}

__global__ __launch_bounds__(256)
void wtrans_kernel(const float* __restrict__ W)
{
    int idx = blockIdx.x * 256 + threadIdx.x;
    if (idx < DN * SN) {
        int d = idx >> 8, s = idx & 255;
        g_WT[s * DN + d] = __float2half(W[idx]);
    }
}

__global__ __launch_bounds__(256)
void imgtrans_kernel(const float* __restrict__ img_g)
{
    __shared__ float t[64 * 37];
    const int i  = blockIdx.x;
    const int db = blockIdx.y;
    for (int idx = threadIdx.x; idx < RN * 64; idx += 256) {
        int r = idx >> 6, dd = idx & 63;
        t[dd * 37 + r] = img_g[((size_t)i * RN + r) * DN + db * 64 + dd];
    }
    __syncthreads();
    __half* out = g_imgT + ((size_t)i * DN + db * 64) * RPAD;
    for (int idx = threadIdx.x; idx < 64 * (RPAD / 2); idx += 256) {
        int dd = idx / (RPAD / 2), rq = idx - dd * (RPAD / 2);
        int r = 2 * rq;
        float v0 = (r     < RN) ? t[dd * 37 + r]     : 0.f;
        float v1 = (r + 1 < RN) ? t[dd * 37 + r + 1] : 0.f;
        *(__half2*)(out + dd * RPAD + r) = __floats2half2_rn(v0, v1);
    }
}

// ---------------- main fused kernel ----------------
__global__ __launch_bounds__(NT, 2)
void graphembt_kernel(const float* __restrict__ img_g,
                      const float* __restrict__ cap_g,
                      const int*   __restrict__ lens_g,
                      const float* __restrict__ b_g,
                      float*       __restrict__ out_g)
{
    extern __shared__ float sm[];
    const int i    = blockIdx.x;
    const int c    = blockIdx.y;
    const int tid  = threadIdx.x;
    const int w    = tid >> 5;       // 0..7
    const int lane = tid & 31;
    const int gq   = lane >> 2;      // 0..7
    const int tg   = lane & 3;       // 0..3
    const int l15  = lane & 15;
    const int l7   = lane & 7;
    const int khA  = lane >> 4;          // A-frag k-half (x4)
    const int khB  = (lane >> 3) & 1;    // B-frag k-half
    const int jm   = (lane >> 4) & 1;    // B-x4 n-octet select

    const uint32_t sb = smem_u32(sm);

    const float* imgB = img_g + (size_t)i * (RN * DN);
    const float* capB = cap_g + (size_t)c * (LN * DN);

    if (tid < SN / 4)
        *(float4*)(sm + OFF_B + tid * 4) = *(const float4*)(b_g + tid * 4);

    // ======== Phase 1: attn[r][l], cp.async double-buffered 64-d chunks ====
    const int rg1 = tid / 20, lg1 = tid - (tid / 20) * 20;
    const int r0 = 3 * rg1, l0 = 2 * lg1;
    u64 p2[3][2];
    #pragma unroll
    for (int a = 0; a < 3; a++) { p2[a][0] = 0ull; p2[a][1] = 0ull; }

    for (int idx = tid; idx < RN * (DC1 / 4); idx += NT) {
        int r = idx >> 4, d4 = idx & 15;
        CP16(sb + (P1_IMG0 + r * SP1 + d4 * 4) * 4, imgB + r * DN + d4 * 4);
    }
    for (int idx = tid; idx < LN * (DC1 / 4); idx += NT) {
        int l = idx >> 4, d4 = idx & 15;
        CP16(sb + (P1_CAP0 + l * SP1 + d4 * 4) * 4, capB + l * DN + d4 * 4);
    }
    CP_COMMIT();

    for (int k = 0; k < NCH1; k++) {
        const int cur = k & 1;
        const int imgC = cur ? P1_IMG1 : P1_IMG0;
        const int capC = cur ? P1_CAP1 : P1_CAP0;
        CP_WAIT0();
        __syncthreads();
        if (k + 1 < NCH1) {
            const int imgN = cur ? P1_IMG0 : P1_IMG1;
            const int capN = cur ? P1_CAP0 : P1_CAP1;
            const int dof = (k + 1) * DC1;
            for (int idx = tid; idx < RN * (DC1 / 4); idx += NT) {
                int r = idx >> 4, d4 = idx & 15;
                CP16(sb + (imgN + r * SP1 + d4 * 4) * 4,
                     imgB + r * DN + dof + d4 * 4);
            }
            for (int idx = tid; idx < LN * (DC1 / 4); idx += NT) {
                int l = idx >> 4, d4 = idx & 15;
                CP16(sb + (capN + l * SP1 + d4 * 4) * 4,
                     capB + l * DN + dof + d4 * 4);
            }
            CP_COMMIT();
        }
        if (tid < 240) {
            #pragma unroll 2
            for (int d4 = 0; d4 < DC1; d4 += 4) {
                ulonglong2 av[3], cv[2];
                #pragma unroll
                for (int a = 0; a < 3; a++)
                    av[a] = *(const ulonglong2*)(sm + imgC + (r0 + a) * SP1 + d4);
                #pragma unroll
                for (int b = 0; b < 2; b++)
                    cv[b] = *(const ulonglong2*)(sm + capC + (l0 + b) * SP1 + d4);
                #pragma unroll
                for (int a = 0; a < 3; a++)
                    #pragma unroll
                    for (int b = 0; b < 2; b++) {
                        FMA2(p2[a][b], av[a].x, cv[b].x, p2[a][b]);
                        FMA2(p2[a][b], av[a].y, cv[b].y, p2[a][b]);
                    }
            }
        }
    }
    __syncthreads();
    float* sAttn = sm + OFF_ATTN;
    if (tid < 240) {
        #pragma unroll
        for (int a = 0; a < 3; a++)
            #pragma unroll
            for (int b = 0; b < 2; b++) {
                float lo, hi;
                UNPK(lo, hi, p2[a][b]);
                sAttn[(r0 + a) * 41 + (l0 + b)] = lo + hi;
            }
    }
    __syncthreads();

    // ======== Phase 2a: leaky+l2norm(l); stage Gram concurrently ========
    float* sGrm = sm + OFF_GRAM;
    if (tid < RN) {
        float ss = 0.f;
        #pragma unroll 4
        for (int l = 0; l < LN; l++) {
            float x = sAttn[tid * 41 + l];
            x = (x > 0.f) ? x : 0.1f * x;
            sAttn[tid * 41 + l] = x;
            ss = fmaf(x, x, ss);
        }
        float inv = 1.f / (sqrtf(ss) + 1e-8f);
        #pragma unroll 4
        for (int l = 0; l < LN; l++) sAttn[tid * 41 + l] *= inv;
    }
    for (int idx = tid; idx < RN * RN; idx += NT) {
        int r = idx / RN, r2 = idx - (idx / RN) * RN;
        sGrm[r * 37 + r2] = g_gram[i * RN * RN + idx];
    }
    __syncthreads();

    // ======== Phase 2b: softmax over r -> sAT[l][r] (fp32) ========
    float* sAT = sm + OFF_AT;
    if (tid < LN) {
        float mx = -1e30f;
        #pragma unroll 4
        for (int r = 0; r < RN; r++)
            mx = fmaxf(mx, sAttn[r * 41 + tid] * 9.0f);
        float ev[RN];
        float sum = 0.f;
        #pragma unroll 4
        for (int r = 0; r < RN; r++) {
            float e = expf(sAttn[r * 41 + tid] * 9.0f - mx);
            ev[r] = e;
            sum += e;
        }
        float inv = 1.f / sum;
        #pragma unroll 4
        for (int r = 0; r < RN; r++) sAT[tid * 40 + r] = ev[r] * inv;
    }
    __syncthreads();

    // ======== ssq via Gram + build fp16 sATh ========
    float* sInv = sm + OFF_INV;
    #pragma unroll
    for (int q = 0; q < 5; q++) {
        const int l = w + 8 * q;
        float t = 0.f, t2 = 0.f;
        #pragma unroll 4
        for (int rp = 0; rp < RN; rp++) {
            float a = sAT[l * 40 + rp];
            t = fmaf(sGrm[lane * 37 + rp], a, t);
            if (lane < 4)
                t2 = fmaf(sGrm[(32 + lane) * 37 + rp], a, t2);
        }
        float part = sAT[l * 40 + lane] * t;
        if (lane < 4) part += sAT[l * 40 + 32 + lane] * t2;
        float ss = warp_sum(part);
        if (lane == 0) sInv[l] = 1.f / (sqrtf(ss) + 1e-8f);
    }
    {
        __half* sATh = (__half*)(sm + OFF_ATH);
        for (int idx = tid; idx < 48 * (ITH / 2); idx += NT) {
            int l = idx / (ITH / 2), rq = idx - l * (ITH / 2);
            int r = 2 * rq;
            float v0 = (l < LN && r     < RN) ? sAT[l * 40 + r]     : 0.f;
            float v1 = (l < LN && r + 1 < RN) ? sAT[l * 40 + r + 1] : 0.f;
            *(__half2*)(sATh + l * ITH + r) = __floats2half2_rn(v0, v1);
        }
    }
    __syncthreads();

    // zero A tile (rows 40..47 stay zero)
    for (int idx = tid; idx < (48 * ATH) / 8; idx += NT) {
        float4 z = make_float4(0.f, 0.f, 0.f, 0.f);
        *(float4*)(sm + OFF_A + idx * 4) = z;
    }
    float invq[5];
    #pragma unroll
    for (int q = 0; q < 5; q++) invq[q] = sInv[gq + 8 * q];

    // prologue: stage chunk 0 (WT + imgT)
    for (int idx = tid; idx < SN * 8; idx += NT) {
        int s = idx >> 3, q = idx & 7;
        CP16(sb + OFF_WT0 * 4 + s * (WTH * 2) + q * 16,
             (const char*)(g_WT + (size_t)s * DN) + q * 16);
    }
    for (int idx = tid; idx < DC3 * 6; idx += NT) {
        int d = idx / 6, q = idx - d * 6;
        CP16(sb + OFF_IT0 * 4 + d * (ITH * 2) + q * 16,
             (const char*)(g_imgT + ((size_t)i * DN + d) * RPAD) + q * 16);
    }
    CP_COMMIT();

    // precomputed ldmatrix/stmatrix address bases (byte, shared space)
    const uint32_t aATh = sb + OFF_ATH * 4 + l15 * (ITH * 2) + khA * 16;  // + mt*16*ITH*2 + kt*32
    const uint32_t aA   = sb + OFF_A   * 4 + l15 * (ATH * 2) + khA * 16;  // + mt*16*ATH*2 + ks*32
    const uint32_t aITb = (8 * w + l7) * (ITH * 2) + khB * 16;            // + itC*4 + kt*32
    const uint32_t aWTb = (32 * w + 8 * jm + l7) * (WTH * 2) + khB * 16;  // + wtC*4 + jb*8*WTH*2 + ks*32
    const uint32_t stA  = sb + OFF_A * 4 + l15 * (ATH * 2) + w * 16;      // + mt*16*ATH*2
    const uint32_t stA2 = sb + OFF_A * 4 + (32 + l7) * (ATH * 2) + w * 16;

    // ======== Phase 3: 16 chunks of 64 d: wc(mma) -> sim -> GEMM(mma) =====
    float acc[3][4][4];
    #pragma unroll
    for (int mt = 0; mt < 3; mt++)
        #pragma unroll
        for (int j = 0; j < 4; j++)
            #pragma unroll
            for (int q = 0; q < 4; q++) acc[mt][j][q] = 0.f;

    for (int ch = 0; ch < NCH3; ch++) {
        const int cur = ch & 1;
        const int wtC = cur ? OFF_WT1 : OFF_WT0;
        const int itC = cur ? OFF_IT1 : OFF_IT0;

        CP_WAIT0();
        __syncthreads();

        if (ch + 1 < NCH3) {
            const int wtN = cur ? OFF_WT0 : OFF_WT1;
            const int itN = cur ? OFF_IT0 : OFF_IT1;
            const int dof = (ch + 1) * DC3;
            for (int idx = tid; idx < SN * 8; idx += NT) {
                int s = idx >> 3, q = idx & 7;
                CP16(sb + wtN * 4 + s * (WTH * 2) + q * 16,
                     (const char*)(g_WT + (size_t)s * DN + dof) + q * 16);
            }
            for (int idx = tid; idx < DC3 * 6; idx += NT) {
                int d = idx / 6, q = idx - d * 6;
                CP16(sb + itN * 4 + d * (ITH * 2) + q * 16,
                     (const char*)(g_imgT + ((size_t)i * DN + dof + d) * RPAD) + q * 16);
            }
            CP_COMMIT();
        }

        // cap for this thread's sim positions
        float2 capr[5];
        {
            const float* cp = capB + ch * DC3 + 8 * w + 2 * tg;
            #pragma unroll
            for (int q = 0; q < 5; q++)
                capr[q] = *(const float2*)(cp + (size_t)(gq + 8 * q) * DN);
        }

        // wc via mma (ldmatrix frags): warp w -> d in [8w, 8w+8)
        float wca[3][4];
        #pragma unroll
        for (int mt = 0; mt < 3; mt++)
            #pragma unroll
            for (int q = 0; q < 4; q++) wca[mt][q] = 0.f;
        {
            const uint32_t itB = sb + itC * 4 + aITb;
            #pragma unroll
            for (int kt = 0; kt < 3; kt++) {
                uint32_t bf[2];
                LDSM_X2(bf[0], bf[1], itB + kt * 32);
                #pragma unroll
                for (int mt = 0; mt < 3; mt++) {
                    uint32_t af[4];
                    LDSM_X4(af[0], af[1], af[2], af[3],
                            aATh + mt * 16 * (ITH * 2) + kt * 32);
                    MMA_F16(wca[mt], af, bf);
                }
            }
        }
        // sim = (wc*inv - cap)^2 -> fp16 A tile via stmatrix
        {
            #pragma unroll
            for (int mt = 0; mt < 2; mt++) {
                float v0 = fmaf(wca[mt][0], invq[2 * mt],     -capr[2 * mt].x);
                float v1 = fmaf(wca[mt][1], invq[2 * mt],     -capr[2 * mt].y);
                float v2 = fmaf(wca[mt][2], invq[2 * mt + 1], -capr[2 * mt + 1].x);
                float v3 = fmaf(wca[mt][3], invq[2 * mt + 1], -capr[2 * mt + 1].y);
                STSM_X2(stA + mt * 16 * (ATH * 2),
                        h2u(v0 * v0, v1 * v1), h2u(v2 * v2, v3 * v3));
            }
            float v0 = fmaf(wca[2][0], invq[4], -capr[4].x);
            float v1 = fmaf(wca[2][1], invq[4], -capr[4].y);
            STSM_X1(stA2, h2u(v0 * v0, v1 * v1));
        }
        __syncthreads();   // sim tile ready

        // GEMM (ldmatrix frags): warp w -> n slice [32w, 32w+32), k = 64
        {
            const uint32_t wtB = sb + wtC * 4 + aWTb;
            #pragma unroll
            for (int ks = 0; ks < 4; ks++) {
                uint32_t af[3][4];
                #pragma unroll
                for (int mt = 0; mt < 3; mt++)
                    LDSM_X4(af[mt][0], af[mt][1], af[mt][2], af[mt][3],
                            aA + mt * 16 * (ATH * 2) + ks * 32);
                uint32_t bf[4][2];
                #pragma unroll
                for (int jb = 0; jb < 4; jb += 2) {
                    uint32_t b0, b1, b2, b3;
                    LDSM_X4(b0, b1, b2, b3,
                            wtB + jb * 8 * (WTH * 2) + ks * 32);
                    bf[jb][0] = b0; bf[jb][1] = b1;
                    bf[jb + 1][0] = b2; bf[jb + 1][1] = b3;
                }
                #pragma unroll
                for (int mt = 0; mt < 3; mt++)
                    #pragma unroll
                    for (int j = 0; j < 4; j++)
                        MMA_F16(acc[mt][j], af[mt], bf[j]);
            }
        }
    }

    // ======== Epilogue: +b, relu, per-row ssq (quad shfl), norm, store ====
    __syncthreads();
    float* sRed = sm + OFF_RED;
    #pragma unroll
    for (int mt = 0; mt < 3; mt++) {
        #pragma unroll
        for (int half = 0; half < 2; half++) {
            const int l = mt * 16 + gq + 8 * half;
            float ssq = 0.f;
            #pragma unroll
            for (int j = 0; j < 4; j++) {
                const int s = 32 * w + 8 * j + 2 * tg;
                float x0 = fmaxf(acc[mt][j][2 * half]     + sm[OFF_B + s],     0.f);
                float x1 = fmaxf(acc[mt][j][2 * half + 1] + sm[OFF_B + s + 1], 0.f);
                acc[mt][j][2 * half]     = x0;
                acc[mt][j][2 * half + 1] = x1;
                ssq = fmaf(x0, x0, ssq);
                ssq = fmaf(x1, x1, ssq);
            }
            ssq += __shfl_xor_sync(0xffffffffu, ssq, 1);
            ssq += __shfl_xor_sync(0xffffffffu, ssq, 2);
            if (tg == 0 && l < 48) sRed[l * 8 + w] = ssq;
        }
    }
    __syncthreads();
    const int clen = lens_g[c];
    if (tid < LN) {
        float ss = 0.f;
        #pragma unroll
        for (int q = 0; q < 8; q++) ss += sRed[tid * 8 + q];
        float inv = 1.f / (sqrtf(ss) + 1e-8f);
        sInv[tid] = (tid < clen) ? inv : 0.f;
    }
    __syncthreads();

    float* outB = out_g + (size_t)(c * IN_N + i) * (LN * SN);
    #pragma unroll
    for (int mt = 0; mt < 3; mt++) {
        #pragma unroll
        for (int half = 0; half < 2; half++) {
            const int l = mt * 16 + gq + 8 * half;
            if (l < LN) {
                float inv = sInv[l];
                #pragma unroll
                for (int j = 0; j < 4; j++) {
                    const int s = 32 * w + 8 * j + 2 * tg;
                    float2 o;
                    o.x = acc[mt][j][2 * half]     * inv;
                    o.y = acc[mt][j][2 * half + 1] * inv;
                    *(float2*)(outB + (size_t)l * SN + s) = o;
                }
            }
        }
    }
}

extern "C" void kernel_launch(void* const* d_in, const int* in_sizes, int n_in,
                              void* d_out, int out_size)
{
    const float* img  = (const float*)d_in[0];
    const float* cap  = (const float*)d_in[1];
    const int*   lens = (const int*)  d_in[2];
    const float* W    = (const float*)d_in[5];
    const float* b    = (const float*)d_in[6];
    float* out = (float*)d_out;
    (void)in_sizes; (void)n_in; (void)out_size;

    cudaFuncSetAttribute(graphembt_kernel,
                         cudaFuncAttributeMaxDynamicSharedMemorySize,
                         SMEM_FLOATS * sizeof(float));

    dim3 ggrid(IN_N, (RN * RN) / 8);
    gram_kernel<<<ggrid, 256>>>(img);
    wtrans_kernel<<<(DN * SN + 255) / 256, 256>>>(W);
    dim3 tgrid(IN_N, DN / 64);
    imgtrans_kernel<<<tgrid, 256>>>(img);
    dim3 grid(IN_N, CN);
    graphembt_kernel<<<grid, NT, SMEM_FLOATS * sizeof(float)>>>(
        img, cap, lens, b, out);
}

// round 15
// speedup vs baseline: 2.2408x; 1.4570x over previous
#include <cuda_runtime.h>
#include <cuda_fp16.h>
#include <math.h>
#include <stdint.h>

typedef unsigned long long u64;

#define CN 64
#define IN_N 64
#define RN 36
#define LN 40
#define DN 1024
#define SN 256
#define NT 256

#define DC3 64
#define NCH3 (DN/DC3)      // 16 chunks
#define DC1 64
#define NCH1 (DN/DC1)      // 16 chunks (phase 1)
#define WTH 72             // WT tile stride (halves)
#define ATH 72             // A (sim) tile stride (halves)
#define ITH 56             // imgT tile stride (halves)
#define P1S 72             // phase-1 tile stride (halves)
#define RPAD 48

// ---- smem float offsets ----
#define OFF_WT0   0            // 256x72 halves = 9216 floats
#define OFF_WT1   9216
#define OFF_IT0   18432       // 64x56 halves = 1792 floats
#define OFF_IT1   20224
#define OFF_A     22016       // 48x72 halves = 1728 floats
#define OFF_ATH   23744       // 48x56 halves = 1344 floats
#define OFF_AT    25088       // 40x40 fp32
#define OFF_INV   26688       // 48
#define OFF_RED   26736       // 48x8
#define OFF_B     27120       // 256
#define SMEM_FLOATS 27392     // 109568 B -> 2 CTAs/SM
// phase-1 unions (dead by phase 3):
//  tiles: buf0 @0: imgH(1728f) imgL(1728) capH(1440) capL(1440) = 6336 f
//         buf1 @6336..12672  (inside WT region)
//  partials: 8 x 1921 f = 15368  (reused after tiles dead)
#define P1_BUF1   6336
#define P1_IL     1728
#define P1_CH     3456
#define P1_CL     4896
#define OFF_ATTN  18432       // 36x41 (IT region)
#define OFF_GRAM  22016       // 36x37 (A region)

__device__ float  g_gram[IN_N * RN * RN];
__device__ __half g_WT[SN * DN];
__device__ __half g_imgT[IN_N * DN * RPAD];
__device__ __half g_imgH[IN_N * RN * DN];
__device__ __half g_imgL[IN_N * RN * DN];
__device__ __half g_capH[CN * LN * DN];
__device__ __half g_capL[CN * LN * DN];

// ---------------- PTX helpers ----------------
#define MMA_F16(d, a, b) \
    asm volatile("mma.sync.aligned.m16n8k16.row.col.f32.f16.f16.f32 " \
        "{%0,%1,%2,%3}, {%4,%5,%6,%7}, {%8,%9}, {%0,%1,%2,%3};" \
        : "+f"((d)[0]), "+f"((d)[1]), "+f"((d)[2]), "+f"((d)[3]) \
        : "r"((a)[0]), "r"((a)[1]), "r"((a)[2]), "r"((a)[3]), \
          "r"((b)[0]), "r"((b)[1]))
#define CP16(saddr, gptr) \
    asm volatile("cp.async.cg.shared.global [%0], [%1], 16;" \
                 :: "r"(saddr), "l"(gptr) : "memory")
#define CP_COMMIT() asm volatile("cp.async.commit_group;" ::: "memory")
#define CP_WAIT0()  asm volatile("cp.async.wait_group 0;" ::: "memory")
#define LDSM_X4(R0, R1, R2, R3, ADDR) \
    asm volatile("ldmatrix.sync.aligned.m8n8.x4.shared.b16 {%0,%1,%2,%3}, [%4];" \
        : "=r"(R0), "=r"(R1), "=r"(R2), "=r"(R3) : "r"(ADDR))
#define LDSM_X2(R0, R1, ADDR) \
    asm volatile("ldmatrix.sync.aligned.m8n8.x2.shared.b16 {%0,%1}, [%2];" \
        : "=r"(R0), "=r"(R1) : "r"(ADDR))
#define STSM_X2(ADDR, R0, R1) \
    asm volatile("stmatrix.sync.aligned.m8n8.x2.shared.b16 [%0], {%1,%2};" \
        :: "r"(ADDR), "r"(R0), "r"(R1) : "memory")
#define STSM_X1(ADDR, R0) \
    asm volatile("stmatrix.sync.aligned.m8n8.x1.shared.b16 [%0], {%1};" \
        :: "r"(ADDR), "r"(R0) : "memory")

__device__ __forceinline__ uint32_t smem_u32(const void* p) {
    uint32_t a;
    asm("{ .reg .u64 t; cvta.to.shared.u64 t, %1; cvt.u32.u64 %0, t; }"
        : "=r"(a) : "l"(p));
    return a;
}
__device__ __forceinline__ float warp_sum(float v) {
    #pragma unroll
    for (int o = 16; o > 0; o >>= 1) v += __shfl_xor_sync(0xffffffffu, v, o);
    return v;
}
__device__ __forceinline__ uint32_t h2u(float a, float b) {
    __half2 h = __floats2half2_rn(a, b);
    return *(uint32_t*)&h;
}

// ---- one-time prep kernels ----
__global__ __launch_bounds__(256)
void gram_kernel(const float* __restrict__ img_g)
{
    const int i    = blockIdx.x;
    const int widx = blockIdx.y * 8 + (threadIdx.x >> 5);
    const int lane = threadIdx.x & 31;
    const int r  = widx / RN;
    const int r2 = widx - r * RN;
    const float* A = img_g + ((size_t)i * RN + r ) * DN;
    const float* B = img_g + ((size_t)i * RN + r2) * DN;
    float s = 0.f;
    #pragma unroll 8
    for (int q = lane; q < DN; q += 32)
        s = fmaf(__ldg(A + q), __ldg(B + q), s);
    s = warp_sum(s);
    if (lane == 0) g_gram[i * RN * RN + widx] = s;
}

__global__ __launch_bounds__(256)
void wtrans_kernel(const float* __restrict__ W)
{
    int idx = blockIdx.x * 256 + threadIdx.x;
    if (idx < DN * SN) {
        int d = idx >> 8, s = idx & 255;
        g_WT[s * DN + d] = __float2half(W[idx]);
    }
}

__global__ __launch_bounds__(256)
void imgtrans_kernel(const float* __restrict__ img_g)
{
    __shared__ float t[64 * 37];
    const int i  = blockIdx.x;
    const int db = blockIdx.y;
    for (int idx = threadIdx.x; idx < RN * 64; idx += 256) {
        int r = idx >> 6, dd = idx & 63;
        t[dd * 37 + r] = img_g[((size_t)i * RN + r) * DN + db * 64 + dd];
    }
    __syncthreads();
    __half* out = g_imgT + ((size_t)i * DN + db * 64) * RPAD;
    for (int idx = threadIdx.x; idx < 64 * (RPAD / 2); idx += 256) {
        int dd = idx / (RPAD / 2), rq = idx - dd * (RPAD / 2);
        int r = 2 * rq;
        float v0 = (r     < RN) ? t[dd * 37 + r]     : 0.f;
        float v1 = (r + 1 < RN) ? t[dd * 37 + r + 1] : 0.f;
        *(__half2*)(out + dd * RPAD + r) = __floats2half2_rn(v0, v1);
    }
}

__global__ __launch_bounds__(256)
void imghl_kernel(const float* __restrict__ img_g)
{
    size_t idx = (size_t)blockIdx.x * 256 + threadIdx.x;
    if (idx < (size_t)IN_N * RN * DN) {
        float v = img_g[idx];
        __half h = __float2half(v);
        g_imgH[idx] = h;
        g_imgL[idx] = __float2half(v - __half2float(h));
    }
}

__global__ __launch_bounds__(256)
void caphl_kernel(const float* __restrict__ cap_g)
{
    size_t idx = (size_t)blockIdx.x * 256 + threadIdx.x;
    if (idx < (size_t)CN * LN * DN) {
        float v = cap_g[idx];
        __half h = __float2half(v);
        g_capH[idx] = h;
        g_capL[idx] = __float2half(v - __half2float(h));
    }
}

// ---------------- main fused kernel ----------------
__global__ __launch_bounds__(NT, 2)
void graphembt_kernel(const float* __restrict__ cap_g,
                      const int*   __restrict__ lens_g,
                      const float* __restrict__ b_g,
                      float*       __restrict__ out_g)
{
    extern __shared__ float sm[];
    const int i    = blockIdx.x;
    const int c    = blockIdx.y;
    const int tid  = threadIdx.x;
    const int w    = tid >> 5;       // 0..7
    const int lane = tid & 31;
    const int gq   = lane >> 2;      // 0..7
    const int tg   = lane & 3;       // 0..3
    const int l15  = lane & 15;
    const int l7   = lane & 7;
    const int khA  = lane >> 4;
    const int khB  = (lane >> 3) & 1;
    const int jm   = (lane >> 4) & 1;

    const uint32_t sb = smem_u32(sm);
    const float* capB = cap_g + (size_t)c * (LN * DN);

    if (tid < SN / 4)
        *(float4*)(sm + OFF_B + tid * 4) = *(const float4*)(b_g + tid * 4);

    // ======== Phase 1: attn via fp16 hi/lo MMA (3 products) ========
    // per chunk of 64 d: jobs (p, ks): warps 0-3 do (p0, ks=w) + (p2, ks=w);
    // warps 4-7 do (p1, ks=w-4). acc holds full 48x40 partial per warp.
    const __half* iH = g_imgH + (size_t)i * RN * DN;
    const __half* iL = g_imgL + (size_t)i * RN * DN;
    const __half* cH = g_capH + (size_t)c * LN * DN;
    const __half* cL = g_capL + (size_t)c * LN * DN;

    float accA[15][4];
    #pragma unroll
    for (int t = 0; t < 15; t++)
        #pragma unroll
        for (int q = 0; q < 4; q++) accA[t][q] = 0.f;

    const uint32_t aOffA = l15 * (P1S * 2) + khA * 16;          // A-frag lane offset
    const uint32_t bOffX4 = (8 * jm + l7) * (P1S * 2) + khB * 16;
    const uint32_t bOffX2 = (32 + l7) * (P1S * 2) + khB * 16;

    // prologue: stage chunk 0 into buf0
    {
        for (int idx = tid; idx < 288; idx += NT) {
            int r = idx >> 3, q = idx & 7;
            const size_t go = ((size_t)r) * DN;
            CP16(sb + (0) * 4 + r * (P1S * 2) + q * 16, (const char*)(iH + go) + q * 16);
            CP16(sb + (P1_IL) * 4 + r * (P1S * 2) + q * 16, (const char*)(iL + go) + q * 16);
        }
        for (int idx = tid; idx < 320; idx += NT) {
            int l = idx >> 3, q = idx & 7;
            const size_t go = ((size_t)l) * DN;
            CP16(sb + (P1_CH) * 4 + l * (P1S * 2) + q * 16, (const char*)(cH + go) + q * 16);
            CP16(sb + (P1_CL) * 4 + l * (P1S * 2) + q * 16, (const char*)(cL + go) + q * 16);
        }
        CP_COMMIT();
    }

    for (int ch = 0; ch < NCH1; ch++) {
        const int cur = ch & 1;
        const int B0 = cur ? P1_BUF1 : 0;
        CP_WAIT0();
        __syncthreads();
        if (ch + 1 < NCH1) {
            const int BN = cur ? 0 : P1_BUF1;
            const int dof = (ch + 1) * DC1;
            for (int idx = tid; idx < 288; idx += NT) {
                int r = idx >> 3, q = idx & 7;
                const size_t go = ((size_t)r) * DN + dof;
                CP16(sb + (BN) * 4 + r * (P1S * 2) + q * 16, (const char*)(iH + go) + q * 16);
                CP16(sb + (BN + P1_IL) * 4 + r * (P1S * 2) + q * 16, (const char*)(iL + go) + q * 16);
            }
            for (int idx = tid; idx < 320; idx += NT) {
                int l = idx >> 3, q = idx & 7;
                const size_t go = ((size_t)l) * DN + dof;
                CP16(sb + (BN + P1_CH) * 4 + l * (P1S * 2) + q * 16, (const char*)(cH + go) + q * 16);
                CP16(sb + (BN + P1_CL) * 4 + l * (P1S * 2) + q * 16, (const char*)(cL + go) + q * 16);
            }
            CP_COMMIT();
        }

        const int njobs = (w < 4) ? 2 : 1;
        #pragma unroll
        for (int jj = 0; jj < 2; jj++) {
            if (jj < njobs) {
                const int p  = (w < 4) ? (jj == 0 ? 0 : 2) : 1;
                const int ks = (w < 4) ? w : (w - 4);
                const uint32_t aBase = sb + (B0 + ((p == 2) ? P1_IL : 0)) * 4
                                     + aOffA + ks * 32;
                const uint32_t bBase = sb + (B0 + ((p == 1) ? P1_CL : P1_CH)) * 4
                                     + ks * 32;
                uint32_t af[3][4];
                #pragma unroll
                for (int mt = 0; mt < 3; mt++)
                    LDSM_X4(af[mt][0], af[mt][1], af[mt][2], af[mt][3],
                            aBase + mt * 16 * (P1S * 2));
                uint32_t bf[5][2];
                #pragma unroll
                for (int jb = 0; jb < 4; jb += 2) {
                    uint32_t b0, b1, b2, b3;
                    LDSM_X4(b0, b1, b2, b3, bBase + bOffX4 + jb * 8 * (P1S * 2));
                    bf[jb][0] = b0; bf[jb][1] = b1;
                    bf[jb + 1][0] = b2; bf[jb + 1][1] = b3;
                }
                LDSM_X2(bf[4][0], bf[4][1], bBase + bOffX2);
                #pragma unroll
                for (int mt = 0; mt < 3; mt++)
                    #pragma unroll
                    for (int nt = 0; nt < 5; nt++)
                        MMA_F16(accA[mt * 5 + nt], af[mt], bf[nt]);
            }
        }
    }
    __syncthreads();   // phase-1 tiles dead; reuse region for partials

    // store per-warp partials (stride 1921 floats, conflict-free)
    {
        float* sPart = sm + (size_t)w * 1921;
        #pragma unroll
        for (int mt = 0; mt < 3; mt++)
            #pragma unroll
            for (int nt = 0; nt < 5; nt++) {
                const int rr = mt * 16 + gq;
                const int cc = nt * 8 + 2 * tg;
                sPart[rr * 40 + cc]           = accA[mt * 5 + nt][0];
                sPart[rr * 40 + cc + 1]       = accA[mt * 5 + nt][1];
                sPart[(rr + 8) * 40 + cc]     = accA[mt * 5 + nt][2];
                sPart[(rr + 8) * 40 + cc + 1] = accA[mt * 5 + nt][3];
            }
    }
    __syncthreads();
    float* sAttn = sm + OFF_ATTN;
    for (int idx = tid; idx < RN * 40; idx += NT) {
        int r = idx / 40, l = idx - r * 40;
        float s = 0.f;
        #pragma unroll
        for (int q = 0; q < 8; q++) s += sm[q * 1921 + r * 40 + l];
        sAttn[r * 41 + l] = s;
    }
    __syncthreads();

    // ======== Phase 2a: leaky+l2norm(l); stage Gram concurrently ========
    float* sGrm = sm + OFF_GRAM;
    if (tid < RN) {
        float ss = 0.f;
        #pragma unroll 4
        for (int l = 0; l < LN; l++) {
            float x = sAttn[tid * 41 + l];
            x = (x > 0.f) ? x : 0.1f * x;
            sAttn[tid * 41 + l] = x;
            ss = fmaf(x, x, ss);
        }
        float inv = 1.f / (sqrtf(ss) + 1e-8f);
        #pragma unroll 4
        for (int l = 0; l < LN; l++) sAttn[tid * 41 + l] *= inv;
    }
    for (int idx = tid; idx < RN * RN; idx += NT) {
        int r = idx / RN, r2 = idx - (idx / RN) * RN;
        sGrm[r * 37 + r2] = g_gram[i * RN * RN + idx];
    }
    __syncthreads();

    // ======== Phase 2b: softmax over r -> sAT[l][r] (fp32) ========
    float* sAT = sm + OFF_AT;
    if (tid < LN) {
        float mx = -1e30f;
        #pragma unroll 4
        for (int r = 0; r < RN; r++)
            mx = fmaxf(mx, sAttn[r * 41 + tid] * 9.0f);
        float ev[RN];
        float sum = 0.f;
        #pragma unroll 4
        for (int r = 0; r < RN; r++) {
            float e = expf(sAttn[r * 41 + tid] * 9.0f - mx);
            ev[r] = e;
            sum += e;
        }
        float inv = 1.f / sum;
        #pragma unroll 4
        for (int r = 0; r < RN; r++) sAT[tid * 40 + r] = ev[r] * inv;
    }
    __syncthreads();

    // ======== ssq via Gram + build fp16 sATh ========
    float* sInv = sm + OFF_INV;
    #pragma unroll
    for (int q = 0; q < 5; q++) {
        const int l = w + 8 * q;
        float t = 0.f, t2 = 0.f;
        #pragma unroll 4
        for (int rp = 0; rp < RN; rp++) {
            float a = sAT[l * 40 + rp];
            t = fmaf(sGrm[lane * 37 + rp], a, t);
            if (lane < 4)
                t2 = fmaf(sGrm[(32 + lane) * 37 + rp], a, t2);
        }
        float part = sAT[l * 40 + lane] * t;
        if (lane < 4) part += sAT[l * 40 + 32 + lane] * t2;
        float ss = warp_sum(part);
        if (lane == 0) sInv[l] = 1.f / (sqrtf(ss) + 1e-8f);
    }
    {
        __half* sATh = (__half*)(sm + OFF_ATH);
        for (int idx = tid; idx < 48 * (ITH / 2); idx += NT) {
            int l = idx / (ITH / 2), rq = idx - l * (ITH / 2);
            int r = 2 * rq;
            float v0 = (l < LN && r     < RN) ? sAT[l * 40 + r]     : 0.f;
            float v1 = (l < LN && r + 1 < RN) ? sAT[l * 40 + r + 1] : 0.f;
            *(__half2*)(sATh + l * ITH + r) = __floats2half2_rn(v0, v1);
        }
    }
    __syncthreads();

    // zero A tile (rows 40..47 stay zero)
    for (int idx = tid; idx < (48 * ATH) / 8; idx += NT) {
        float4 z = make_float4(0.f, 0.f, 0.f, 0.f);
        *(float4*)(sm + OFF_A + idx * 4) = z;
    }
    float invq[5];
    #pragma unroll
    for (int q = 0; q < 5; q++) invq[q] = sInv[gq + 8 * q];

    // prologue: stage chunk 0 (WT + imgT)
    for (int idx = tid; idx < SN * 8; idx += NT) {
        int s = idx >> 3, q = idx & 7;
        CP16(sb + OFF_WT0 * 4 + s * (WTH * 2) + q * 16,
             (const char*)(g_WT + (size_t)s * DN) + q * 16);
    }
    for (int idx = tid; idx < DC3 * 6; idx += NT) {
        int d = idx / 6, q = idx - d * 6;
        CP16(sb + OFF_IT0 * 4 + d * (ITH * 2) + q * 16,
             (const char*)(g_imgT + ((size_t)i * DN + d) * RPAD) + q * 16);
    }
    CP_COMMIT();

    // ldmatrix/stmatrix address bases
    const uint32_t aATh = sb + OFF_ATH * 4 + l15 * (ITH * 2) + khA * 16;
    const uint32_t aA   = sb + OFF_A   * 4 + l15 * (ATH * 2) + khA * 16;
    const uint32_t aITb = (8 * w + l7) * (ITH * 2) + khB * 16;
    const uint32_t aWTb = (32 * w + 8 * jm + l7) * (WTH * 2) + khB * 16;
    const uint32_t stA  = sb + OFF_A * 4 + l15 * (ATH * 2) + w * 16;
    const uint32_t stA2 = sb + OFF_A * 4 + (32 + l7) * (ATH * 2) + w * 16;

    // ======== Phase 3: 16 chunks of 64 d: wc(mma) -> sim -> GEMM(mma) =====
    float acc[3][4][4];
    #pragma unroll
    for (int mt = 0; mt < 3; mt++)
        #pragma unroll
        for (int j = 0; j < 4; j++)
            #pragma unroll
            for (int q = 0; q < 4; q++) acc[mt][j][q] = 0.f;

    for (int ch = 0; ch < NCH3; ch++) {
        const int cur = ch & 1;
        const int wtC = cur ? OFF_WT1 : OFF_WT0;
        const int itC = cur ? OFF_IT1 : OFF_IT0;

        CP_WAIT0();
        __syncthreads();

        if (ch + 1 < NCH3) {
            const int wtN = cur ? OFF_WT0 : OFF_WT1;
            const int itN = cur ? OFF_IT0 : OFF_IT1;
            const int dof = (ch + 1) * DC3;
            for (int idx = tid; idx < SN * 8; idx += NT) {
                int s = idx >> 3, q = idx & 7;
                CP16(sb + wtN * 4 + s * (WTH * 2) + q * 16,
                     (const char*)(g_WT + (size_t)s * DN + dof) + q * 16);
            }
            for (int idx = tid; idx < DC3 * 6; idx += NT) {
                int d = idx / 6, q = idx - d * 6;
                CP16(sb + itN * 4 + d * (ITH * 2) + q * 16,
                     (const char*)(g_imgT + ((size_t)i * DN + dof + d) * RPAD) + q * 16);
            }
            CP_COMMIT();
        }

        float2 capr[5];
        {
            const float* cp = capB + ch * DC3 + 8 * w + 2 * tg;
            #pragma unroll
            for (int q = 0; q < 5; q++)
                capr[q] = *(const float2*)(cp + (size_t)(gq + 8 * q) * DN);
        }

        // wc via mma (ldmatrix frags): warp w -> d in [8w, 8w+8)
        float wca[3][4];
        #pragma unroll
        for (int mt = 0; mt < 3; mt++)
            #pragma unroll
            for (int q = 0; q < 4; q++) wca[mt][q] = 0.f;
        {
            const uint32_t itB = sb + itC * 4 + aITb;
            #pragma unroll
            for (int kt = 0; kt < 3; kt++) {
                uint32_t bf[2];
                LDSM_X2(bf[0], bf[1], itB + kt * 32);
                #pragma unroll
                for (int mt = 0; mt < 3; mt++) {
                    uint32_t af[4];
                    LDSM_X4(af[0], af[1], af[2], af[3],
                            aATh + mt * 16 * (ITH * 2) + kt * 32);
                    MMA_F16(wca[mt], af, bf);
                }
            }
        }
        {
            #pragma unroll
            for (int mt = 0; mt < 2; mt++) {
                float v0 = fmaf(wca[mt][0], invq[2 * mt],     -capr[2 * mt].x);
                float v1 = fmaf(wca[mt][1], invq[2 * mt],     -capr[2 * mt].y);
                float v2 = fmaf(wca[mt][2], invq[2 * mt + 1], -capr[2 * mt + 1].x);
                float v3 = fmaf(wca[mt][3], invq[2 * mt + 1], -capr[2 * mt + 1].y);
                STSM_X2(stA + mt * 16 * (ATH * 2),
                        h2u(v0 * v0, v1 * v1), h2u(v2 * v2, v3 * v3));
            }
            float v0 = fmaf(wca[2][0], invq[4], -capr[4].x);
            float v1 = fmaf(wca[2][1], invq[4], -capr[4].y);
            STSM_X1(stA2, h2u(v0 * v0, v1 * v1));
        }
        __syncthreads();

        // GEMM (ldmatrix frags): warp w -> n slice [32w, 32w+32), k = 64
        {
            const uint32_t wtB = sb + wtC * 4 + aWTb;
            #pragma unroll
            for (int ks = 0; ks < 4; ks++) {
                uint32_t af[3][4];
                #pragma unroll
                for (int mt = 0; mt < 3; mt++)
                    LDSM_X4(af[mt][0], af[mt][1], af[mt][2], af[mt][3],
                            aA + mt * 16 * (ATH * 2) + ks * 32);
                uint32_t bf[4][2];
                #pragma unroll
                for (int jb = 0; jb < 4; jb += 2) {
                    uint32_t b0, b1, b2, b3;
                    LDSM_X4(b0, b1, b2, b3,
                            wtB + jb * 8 * (WTH * 2) + ks * 32);
                    bf[jb][0] = b0; bf[jb][1] = b1;
                    bf[jb + 1][0] = b2; bf[jb + 1][1] = b3;
                }
                #pragma unroll
                for (int mt = 0; mt < 3; mt++)
                    #pragma unroll
                    for (int j = 0; j < 4; j++)
                        MMA_F16(acc[mt][j], af[mt], bf[j]);
            }
        }
    }

    // ======== Epilogue: +b, relu, per-row ssq (quad shfl), norm, store ====
    __syncthreads();
    float* sRed = sm + OFF_RED;
    #pragma unroll
    for (int mt = 0; mt < 3; mt++) {
        #pragma unroll
        for (int half = 0; half < 2; half++) {
            const int l = mt * 16 + gq + 8 * half;
            float ssq = 0.f;
            #pragma unroll
            for (int j = 0; j < 4; j++) {
                const int s = 32 * w + 8 * j + 2 * tg;
                float x0 = fmaxf(acc[mt][j][2 * half]     + sm[OFF_B + s],     0.f);
                float x1 = fmaxf(acc[mt][j][2 * half + 1] + sm[OFF_B + s + 1], 0.f);
                acc[mt][j][2 * half]     = x0;
                acc[mt][j][2 * half + 1] = x1;
                ssq = fmaf(x0, x0, ssq);
                ssq = fmaf(x1, x1, ssq);
            }
            ssq += __shfl_xor_sync(0xffffffffu, ssq, 1);
            ssq += __shfl_xor_sync(0xffffffffu, ssq, 2);
            if (tg == 0 && l < 48) sRed[l * 8 + w] = ssq;
        }
    }
    __syncthreads();
    const int clen = lens_g[c];
    if (tid < LN) {
        float ss = 0.f;
        #pragma unroll
        for (int q = 0; q < 8; q++) ss += sRed[tid * 8 + q];
        float inv = 1.f / (sqrtf(ss) + 1e-8f);
        sInv[tid] = (tid < clen) ? inv : 0.f;
    }
    __syncthreads();

    float* outB = out_g + (size_t)(c * IN_N + i) * (LN * SN);
    #pragma unroll
    for (int mt = 0; mt < 3; mt++) {
        #pragma unroll
        for (int half = 0; half < 2; half++) {
            const int l = mt * 16 + gq + 8 * half;
            if (l < LN) {
                float inv = sInv[l];
                #pragma unroll
                for (int j = 0; j < 4; j++) {
                    const int s = 32 * w + 8 * j + 2 * tg;
                    float2 o;
                    o.x = acc[mt][j][2 * half]     * inv;
                    o.y = acc[mt][j][2 * half + 1] * inv;
                    *(float2*)(outB + (size_t)l * SN + s) = o;
                }
            }
        }
    }
}

extern "C" void kernel_launch(void* const* d_in, const int* in_sizes, int n_in,
                              void* d_out, int out_size)
{
    const float* img  = (const float*)d_in[0];
    const float* cap  = (const float*)d_in[1];
    const int*   lens = (const int*)  d_in[2];
    const float* W    = (const float*)d_in[5];
    const float* b    = (const float*)d_in[6];
    float* out = (float*)d_out;
    (void)in_sizes; (void)n_in; (void)out_size;

    cudaFuncSetAttribute(graphembt_kernel,
                         cudaFuncAttributeMaxDynamicSharedMemorySize,
                         SMEM_FLOATS * sizeof(float));

    dim3 ggrid(IN_N, (RN * RN) / 8);
    gram_kernel<<<ggrid, 256>>>(img);
    wtrans_kernel<<<(DN * SN + 255) / 256, 256>>>(W);
    dim3 tgrid(IN_N, DN / 64);
    imgtrans_kernel<<<tgrid, 256>>>(img);
    imghl_kernel<<<(IN_N * RN * DN + 255) / 256, 256>>>(img);
    caphl_kernel<<<(CN * LN * DN + 255) / 256, 256>>>(cap);
    dim3 grid(IN_N, CN);
    graphembt_kernel<<<grid, NT, SMEM_FLOATS * sizeof(float)>>>(
        cap, lens, b, out);
}

// round 16
// speedup vs baseline: 2.4087x; 1.0750x over previous
#include <cuda_runtime.h>
#include <cuda_fp16.h>
#include <math.h>
#include <stdint.h>

typedef unsigned long long u64;

#define CN 64
#define IN_N 64
#define RN 36
#define LN 40
#define DN 1024
#define SN 256
#define NT 256

#define DC3 64
#define NCH3 (DN/DC3)      // 16 chunks (phase 3)
#define DC1 128
#define NCH1 (DN/DC1)      // 8 chunks (phase 1)
#define WTH 72             // WT tile stride (halves)
#define ATH 72             // A (sim) tile stride (halves)
#define ITH 56             // imgT tile stride (halves)
#define P1S 136            // phase-1 tile stride (halves), 272B rows
#define RPAD 48

// ---- smem float offsets ----
#define OFF_WT0   0            // 256x72 halves = 9216 floats
#define OFF_WT1   9216
#define OFF_IT0   18432       // 64x56 halves = 1792 floats
#define OFF_IT1   20224
#define OFF_A0    22016       // 48x72 halves = 1728 floats
#define OFF_A1    23744
#define OFF_ATH   25472       // 48x56 halves = 1344 floats
#define OFF_INV   26816       // 48
#define OFF_RED   26864       // 48x8
#define OFF_B     27248       // 256
#define SMEM_FLOATS 27504     // 110016 B -> 2 CTAs/SM
// phase-1/2 unions (time-disjoint):
#define P1B       11968       // buffer 1 base (buffer = 11968 floats)
#define P1_IH     0           // imgH 48x136h = 3264 f (rows 36..47 garbage, discarded)
#define P1_IL     3264
#define P1_CH     6528        // capH 40x136h = 2720 f
#define P1_CL     9248
#define OFF_ATTN  18432       // 36x41 (past partials 0..15368)
#define OFF_GRAM  22016       // 36x37 in A0 region
#define OFF_AT    23348       // 40x40 fp32, ends 24948 < OFF_ATH

__device__ float  g_gram[IN_N * RN * RN];
__device__ __half g_WT[SN * DN];
__device__ __half g_imgT[IN_N * DN * RPAD];
__device__ __half g_imgH[IN_N * RN * DN];
__device__ __half g_imgL[IN_N * RN * DN];
__device__ __half g_capH[CN * LN * DN];
__device__ __half g_capL[CN * LN * DN];

// ---------------- PTX helpers ----------------
#define MMA_F16(d, a, b) \
    asm volatile("mma.sync.aligned.m16n8k16.row.col.f32.f16.f16.f32 " \
        "{%0,%1,%2,%3}, {%4,%5,%6,%7}, {%8,%9}, {%0,%1,%2,%3};" \
        : "+f"((d)[0]), "+f"((d)[1]), "+f"((d)[2]), "+f"((d)[3]) \
        : "r"((a)[0]), "r"((a)[1]), "r"((a)[2]), "r"((a)[3]), \
          "r"((b)[0]), "r"((b)[1]))
#define CP16(saddr, gptr) \
    asm volatile("cp.async.cg.shared.global [%0], [%1], 16;" \
                 :: "r"(saddr), "l"(gptr) : "memory")
#define CP_COMMIT() asm volatile("cp.async.commit_group;" ::: "memory")
#define CP_WAIT0()  asm volatile("cp.async.wait_group 0;" ::: "memory")
#define CP_WAIT1()  asm volatile("cp.async.wait_group 1;" ::: "memory")
#define LDSM_X4(R0, R1, R2, R3, ADDR) \
    asm volatile("ldmatrix.sync.aligned.m8n8.x4.shared.b16 {%0,%1,%2,%3}, [%4];" \
        : "=r"(R0), "=r"(R1), "=r"(R2), "=r"(R3) : "r"(ADDR))
#define LDSM_X2(R0, R1, ADDR) \
    asm volatile("ldmatrix.sync.aligned.m8n8.x2.shared.b16 {%0,%1}, [%2];" \
        : "=r"(R0), "=r"(R1) : "r"(ADDR))
#define STSM_X2(ADDR, R0, R1) \
    asm volatile("stmatrix.sync.aligned.m8n8.x2.shared.b16 [%0], {%1,%2};" \
        :: "r"(ADDR), "r"(R0), "r"(R1) : "memory")
#define STSM_X1(ADDR, R0) \
    asm volatile("stmatrix.sync.aligned.m8n8.x1.shared.b16 [%0], {%1};" \
        :: "r"(ADDR), "r"(R0) : "memory")

__device__ __forceinline__ uint32_t smem_u32(const void* p) {
    uint32_t a;
    asm("{ .reg .u64 t; cvta.to.shared.u64 t, %1; cvt.u32.u64 %0, t; }"
        : "=r"(a) : "l"(p));
    return a;
}
__device__ __forceinline__ float warp_sum(float v) {
    #pragma unroll
    for (int o = 16; o > 0; o >>= 1) v += __shfl_xor_sync(0xffffffffu, v, o);
    return v;
}
__device__ __forceinline__ uint32_t h2u(float a, float b) {
    __half2 h = __floats2half2_rn(a, b);
    return *(uint32_t*)&h;
}

// ---- one-time prep kernels ----
__global__ __launch_bounds__(256)
void gram_kernel(const float* __restrict__ img_g)
{
    const int i    = blockIdx.x;
    const int widx = blockIdx.y * 8 + (threadIdx.x >> 5);
    const int lane = threadIdx.x & 31;
    const int r  = widx / RN;
    const int r2 = widx - r * RN;
    const float* A = img_g + ((size_t)i * RN + r ) * DN;
    const float* B = img_g + ((size_t)i * RN + r2) * DN;
    float s = 0.f;
    #pragma unroll 8
    for (int q = lane; q < DN; q += 32)
        s = fmaf(__ldg(A + q), __ldg(B + q), s);
    s = warp_sum(s);
    if (lane == 0) g_gram[i * RN * RN + widx] = s;
}

__global__ __launch_bounds__(256)
void wtrans_kernel(const float* __restrict__ W)
{
    int idx = blockIdx.x * 256 + threadIdx.x;
    if (idx < DN * SN) {
        int d = idx >> 8, s = idx & 255;
        g_WT[s * DN + d] = __float2half(W[idx]);
    }
}

__global__ __launch_bounds__(256)
void imgtrans_kernel(const float* __restrict__ img_g)
{
    __shared__ float t[64 * 37];
    const int i  = blockIdx.x;
    const int db = blockIdx.y;
    for (int idx = threadIdx.x; idx < RN * 64; idx += 256) {
        int r = idx >> 6, dd = idx & 63;
        t[dd * 37 + r] = img_g[((size_t)i * RN + r) * DN + db * 64 + dd];
    }
    __syncthreads();
    __half* out = g_imgT + ((size_t)i * DN + db * 64) * RPAD;
    for (int idx = threadIdx.x; idx < 64 * (RPAD / 2); idx += 256) {
        int dd = idx / (RPAD / 2), rq = idx - dd * (RPAD / 2);
        int r = 2 * rq;
        float v0 = (r     < RN) ? t[dd * 37 + r]     : 0.f;
        float v1 = (r + 1 < RN) ? t[dd * 37 + r + 1] : 0.f;
        *(__half2*)(out + dd * RPAD + r) = __floats2half2_rn(v0, v1);
    }
}

__global__ __launch_bounds__(256)
void imghl_kernel(const float* __restrict__ img_g)
{
    size_t idx = (size_t)blockIdx.x * 256 + threadIdx.x;
    if (idx < (size_t)IN_N * RN * DN) {
        float v = img_g[idx];
        __half h = __float2half(v);
        g_imgH[idx] = h;
        g_imgL[idx] = __float2half(v - __half2float(h));
    }
}

__global__ __launch_bounds__(256)
void caphl_kernel(const float* __restrict__ cap_g)
{
    size_t idx = (size_t)blockIdx.x * 256 + threadIdx.x;
    if (idx < (size_t)CN * LN * DN) {
        float v = cap_g[idx];
        __half h = __float2half(v);
        g_capH[idx] = h;
        g_capL[idx] = __float2half(v - __half2float(h));
    }
}

// ---------------- main fused kernel ----------------
__global__ __launch_bounds__(NT, 2)
void graphembt_kernel(const float* __restrict__ cap_g,
                      const int*   __restrict__ lens_g,
                      const float* __restrict__ b_g,
                      float*       __restrict__ out_g)
{
    extern __shared__ float sm[];
    const int i    = blockIdx.x;
    const int c    = blockIdx.y;
    const int tid  = threadIdx.x;
    const int w    = tid >> 5;       // 0..7
    const int lane = tid & 31;
    const int gq   = lane >> 2;
    const int tg   = lane & 3;
    const int l15  = lane & 15;
    const int l7   = lane & 7;
    const int khA  = lane >> 4;
    const int khB  = (lane >> 3) & 1;
    const int jm   = (lane >> 4) & 1;

    const uint32_t sb = smem_u32(sm);
    const float* capB = cap_g + (size_t)c * (LN * DN);

    if (tid < SN / 4)
        *(float4*)(sm + OFF_B + tid * 4) = *(const float4*)(b_g + tid * 4);

    // ======== Phase 1: attn via fp16 hi/lo MMA, balanced (3 jobs/warp) ====
    const __half* iH = g_imgH + (size_t)i * RN * DN;
    const __half* iL = g_imgL + (size_t)i * RN * DN;
    const __half* cH = g_capH + (size_t)c * LN * DN;
    const __half* cL = g_capL + (size_t)c * LN * DN;

    float accA[15][4];
    #pragma unroll
    for (int t = 0; t < 15; t++)
        #pragma unroll
        for (int q = 0; q < 4; q++) accA[t][q] = 0.f;

    const uint32_t aOffA  = l15 * (P1S * 2) + khA * 16;
    const uint32_t bOffX4 = (8 * jm + l7) * (P1S * 2) + khB * 16;
    const uint32_t bOffX2 = (32 + l7) * (P1S * 2) + khB * 16;

    // prologue: stage chunk 0 into buf0 (128 d)
    {
        for (int idx = tid; idx < 576; idx += NT) {
            int r = idx >> 4, q = idx & 15;
            const size_t go = (size_t)r * DN;
            CP16(sb + (P1_IH) * 4 + r * (P1S * 2) + q * 16, (const char*)(iH + go) + q * 16);
            CP16(sb + (P1_IL) * 4 + r * (P1S * 2) + q * 16, (const char*)(iL + go) + q * 16);
        }
        for (int idx = tid; idx < 640; idx += NT) {
            int l = idx >> 4, q = idx & 15;
            const size_t go = (size_t)l * DN;
            CP16(sb + (P1_CH) * 4 + l * (P1S * 2) + q * 16, (const char*)(cH + go) + q * 16);
            CP16(sb + (P1_CL) * 4 + l * (P1S * 2) + q * 16, (const char*)(cL + go) + q * 16);
        }
        CP_COMMIT();
    }

    for (int ch = 0; ch < NCH1; ch++) {
        const int B0 = (ch & 1) ? P1B : 0;
        CP_WAIT0();
        __syncthreads();
        if (ch + 1 < NCH1) {
            const int BN = (ch & 1) ? 0 : P1B;
            const int dof = (ch + 1) * DC1;
            for (int idx = tid; idx < 576; idx += NT) {
                int r = idx >> 4, q = idx & 15;
                const size_t go = (size_t)r * DN + dof;
                CP16(sb + (BN + P1_IH) * 4 + r * (P1S * 2) + q * 16, (const char*)(iH + go) + q * 16);
                CP16(sb + (BN + P1_IL) * 4 + r * (P1S * 2) + q * 16, (const char*)(iL + go) + q * 16);
            }
            for (int idx = tid; idx < 640; idx += NT) {
                int l = idx >> 4, q = idx & 15;
                const size_t go = (size_t)l * DN + dof;
                CP16(sb + (BN + P1_CH) * 4 + l * (P1S * 2) + q * 16, (const char*)(cH + go) + q * 16);
                CP16(sb + (BN + P1_CL) * 4 + l * (P1S * 2) + q * 16, (const char*)(cL + go) + q * 16);
            }
            CP_COMMIT();
        }

        // warp w handles k-slice ks=w for all three products
        {
            const uint32_t kOff = w * 32;   // 16 halves per ks
            const uint32_t aH = sb + (B0 + P1_IH) * 4 + aOffA + kOff;
            const uint32_t aL = sb + (B0 + P1_IL) * 4 + aOffA + kOff;
            const uint32_t bH = sb + (B0 + P1_CH) * 4 + kOff;
            const uint32_t bL = sb + (B0 + P1_CL) * 4 + kOff;

            uint32_t afH[3][4];
            #pragma unroll
            for (int mt = 0; mt < 3; mt++)
                LDSM_X4(afH[mt][0], afH[mt][1], afH[mt][2], afH[mt][3],
                        aH + mt * 16 * (P1S * 2));
            uint32_t bfH[5][2];
            #pragma unroll
            for (int jb = 0; jb < 4; jb += 2) {
                uint32_t b0, b1, b2, b3;
                LDSM_X4(b0, b1, b2, b3, bH + bOffX4 + jb * 8 * (P1S * 2));
                bfH[jb][0] = b0; bfH[jb][1] = b1;
                bfH[jb + 1][0] = b2; bfH[jb + 1][1] = b3;
            }
            LDSM_X2(bfH[4][0], bfH[4][1], bH + bOffX2);
            uint32_t bfL[5][2];
            #pragma unroll
            for (int jb = 0; jb < 4; jb += 2) {
                uint32_t b0, b1, b2, b3;
                LDSM_X4(b0, b1, b2, b3, bL + bOffX4 + jb * 8 * (P1S * 2));
                bfL[jb][0] = b0; bfL[jb][1] = b1;
                bfL[jb + 1][0] = b2; bfL[jb + 1][1] = b3;
            }
            LDSM_X2(bfL[4][0], bfL[4][1], bL + bOffX2);

            // p0: imgH x capH ; p1: imgH x capL
            #pragma unroll
            for (int mt = 0; mt < 3; mt++)
                #pragma unroll
                for (int nt = 0; nt < 5; nt++) {
                    MMA_F16(accA[mt * 5 + nt], afH[mt], bfH[nt]);
                    MMA_F16(accA[mt * 5 + nt], afH[mt], bfL[nt]);
                }
            // p2: imgL x capH
            uint32_t afL[3][4];
            #pragma unroll
            for (int mt = 0; mt < 3; mt++)
                LDSM_X4(afL[mt][0], afL[mt][1], afL[mt][2], afL[mt][3],
                        aL + mt * 16 * (P1S * 2));
            #pragma unroll
            for (int mt = 0; mt < 3; mt++)
                #pragma unroll
                for (int nt = 0; nt < 5; nt++)
                    MMA_F16(accA[mt * 5 + nt], afL[mt], bfH[nt]);
        }
    }
    __syncthreads();   // phase-1 tiles dead; reuse region for partials

    {
        float* sPart = sm + (size_t)w * 1921;
        #pragma unroll
        for (int mt = 0; mt < 3; mt++)
            #pragma unroll
            for (int nt = 0; nt < 5; nt++) {
                const int rr = mt * 16 + gq;
                const int cc = nt * 8 + 2 * tg;
                sPart[rr * 40 + cc]           = accA[mt * 5 + nt][0];
                sPart[rr * 40 + cc + 1]       = accA[mt * 5 + nt][1];
                sPart[(rr + 8) * 40 + cc]     = accA[mt * 5 + nt][2];
                sPart[(rr + 8) * 40 + cc + 1] = accA[mt * 5 + nt][3];
            }
    }
    __syncthreads();
    float* sAttn = sm + OFF_ATTN;
    for (int idx = tid; idx < RN * 40; idx += NT) {
        int r = idx / 40, l = idx - r * 40;
        float s = 0.f;
        #pragma unroll
        for (int q = 0; q < 8; q++) s += sm[q * 1921 + r * 40 + l];
        sAttn[r * 41 + l] = s;
    }
    __syncthreads();

    // ======== Phase 2a: leaky+l2norm(l); stage Gram concurrently ========
    float* sGrm = sm + OFF_GRAM;
    if (tid < RN) {
        float ss = 0.f;
        #pragma unroll 4
        for (int l = 0; l < LN; l++) {
            float x = sAttn[tid * 41 + l];
            x = (x > 0.f) ? x : 0.1f * x;
            sAttn[tid * 41 + l] = x;
            ss = fmaf(x, x, ss);
        }
        float inv = 1.f / (sqrtf(ss) + 1e-8f);
        #pragma unroll 4
        for (int l = 0; l < LN; l++) sAttn[tid * 41 + l] *= inv;
    }
    for (int idx = tid; idx < RN * RN; idx += NT) {
        int r = idx / RN, r2 = idx - (idx / RN) * RN;
        sGrm[r * 37 + r2] = g_gram[i * RN * RN + idx];
    }
    __syncthreads();

    // ======== Phase 2b: softmax over r -> sAT[l][r] (fp32) ========
    float* sAT = sm + OFF_AT;
    if (tid < LN) {
        float mx = -1e30f;
        #pragma unroll 4
        for (int r = 0; r < RN; r++)
            mx = fmaxf(mx, sAttn[r * 41 + tid] * 9.0f);
        float ev[RN];
        float sum = 0.f;
        #pragma unroll 4
        for (int r = 0; r < RN; r++) {
            float e = expf(sAttn[r * 41 + tid] * 9.0f - mx);
            ev[r] = e;
            sum += e;
        }
        float inv = 1.f / sum;
        #pragma unroll 4
        for (int r = 0; r < RN; r++) sAT[tid * 40 + r] = ev[r] * inv;
    }
    __syncthreads();

    // ======== ssq via Gram + build fp16 sATh ========
    float* sInv = sm + OFF_INV;
    #pragma unroll
    for (int q = 0; q < 5; q++) {
        const int l = w + 8 * q;
        float t = 0.f, t2 = 0.f;
        #pragma unroll 4
        for (int rp = 0; rp < RN; rp++) {
            float a = sAT[l * 40 + rp];
            t = fmaf(sGrm[lane * 37 + rp], a, t);
            if (lane < 4)
                t2 = fmaf(sGrm[(32 + lane) * 37 + rp], a, t2);
        }
        float part = sAT[l * 40 + lane] * t;
        if (lane < 4) part += sAT[l * 40 + 32 + lane] * t2;
        float ss = warp_sum(part);
        if (lane == 0) sInv[l] = 1.f / (sqrtf(ss) + 1e-8f);
    }
    {
        __half* sATh = (__half*)(sm + OFF_ATH);
        for (int idx = tid; idx < 48 * (ITH / 2); idx += NT) {
            int l = idx / (ITH / 2), rq = idx - l * (ITH / 2);
            int r = 2 * rq;
            float v0 = (l < LN && r     < RN) ? sAT[l * 40 + r]     : 0.f;
            float v1 = (l < LN && r + 1 < RN) ? sAT[l * 40 + r + 1] : 0.f;
            *(__half2*)(sATh + l * ITH + r) = __floats2half2_rn(v0, v1);
        }
    }
    __syncthreads();   // sGrm/sAT consumed -> A-tile region free

    // zero both A tiles (rows 40..47 must stay zero)
    for (int idx = tid; idx < 864; idx += NT) {
        float4 z = make_float4(0.f, 0.f, 0.f, 0.f);
        *(float4*)(sm + OFF_A0 + idx * 4) = z;
    }
    float invq[5];
    #pragma unroll
    for (int q = 0; q < 5; q++) invq[q] = sInv[gq + 8 * q];
    __syncthreads();   // A tiles zeroed before any warp's stmatrix/ldmatrix

    // per-warp staging bases
    const __half* gWTw = g_WT + (size_t)(32 * w) * DN;        // warp's 32 WT rows
    const __half* gITw = g_imgT + ((size_t)i * DN + 8 * w) * RPAD;  // +d*RPAD

    // prologue: per-warp stage chunk 0 (WT rows 32w.., IT rows d=8w..8w+8)
    {
        for (int t = lane; t < 256; t += 32) {            // 32 rows x 8 cp
            int sl = t >> 3, q = t & 7;
            CP16(sb + OFF_WT0 * 4 + (32 * w + sl) * (WTH * 2) + q * 16,
                 (const char*)(gWTw + (size_t)sl * DN) + q * 16);
        }
        for (int t = lane; t < 48; t += 32) {             // 8 rows x 6 cp
            int dl = t / 6, q = t - dl * 6;
            CP16(sb + OFF_IT0 * 4 + (8 * w + dl) * (ITH * 2) + q * 16,
                 (const char*)(gITw + (size_t)dl * RPAD) + q * 16);
        }
        CP_COMMIT();
    }

    // ldmatrix/stmatrix lane offsets
    const uint32_t aAOff = l15 * (ATH * 2) + khA * 16;
    const uint32_t aATh  = sb + OFF_ATH * 4 + l15 * (ITH * 2) + khA * 16;
    const uint32_t aITb  = (8 * w + l7) * (ITH * 2) + khB * 16;
    const uint32_t aWTb  = (32 * w + 8 * jm + l7) * (WTH * 2) + khB * 16;
    const uint32_t stAOff  = l15 * (ATH * 2) + w * 16;
    const uint32_t stA2Off = (32 + l7) * (ATH * 2) + w * 16;

    // ======== Phase 3: per-warp staged, 1 sync/chunk ========
    float acc[3][4][4];
    #pragma unroll
    for (int mt = 0; mt < 3; mt++)
        #pragma unroll
        for (int j = 0; j < 4; j++)
            #pragma unroll
            for (int q = 0; q < 4; q++) acc[mt][j][q] = 0.f;

    for (int ch = 0; ch < NCH3; ch++) {
        const int cur = ch & 1;
        const int wtC = cur ? OFF_WT1 : OFF_WT0;
        const int itC = cur ? OFF_IT1 : OFF_IT0;
        const int aC  = cur ? OFF_A1  : OFF_A0;

        // stage(ch+1) per-warp, then wait for stage(ch)
        if (ch + 1 < NCH3) {
            const int wtN = cur ? OFF_WT0 : OFF_WT1;
            const int itN = cur ? OFF_IT0 : OFF_IT1;
            const int dof = (ch + 1) * DC3;
            for (int t = lane; t < 256; t += 32) {
                int sl = t >> 3, q = t & 7;
                CP16(sb + wtN * 4 + (32 * w + sl) * (WTH * 2) + q * 16,
                     (const char*)(gWTw + (size_t)sl * DN + dof) + q * 16);
            }
            for (int t = lane; t < 48; t += 32) {
                int dl = t / 6, q = t - dl * 6;
                CP16(sb + itN * 4 + (8 * w + dl) * (ITH * 2) + q * 16,
                     (const char*)(gITw + (size_t)(dof + dl) * RPAD) + q * 16);
            }
            CP_COMMIT();
            CP_WAIT1();
        } else {
            CP_WAIT0();
        }
        __syncwarp();

        // cap values for this thread's sim positions
        float2 capr[5];
        {
            const float* cp = capB + ch * DC3 + 8 * w + 2 * tg;
            #pragma unroll
            for (int q = 0; q < 5; q++)
                capr[q] = *(const float2*)(cp + (size_t)(gq + 8 * q) * DN);
        }

        // wc via mma: warp w -> d in [8w, 8w+8)
        float wca[3][4];
        #pragma unroll
        for (int mt = 0; mt < 3; mt++)
            #pragma unroll
            for (int q = 0; q < 4; q++) wca[mt][q] = 0.f;
        {
            const uint32_t itB = sb + itC * 4 + aITb;
            #pragma unroll
            for (int kt = 0; kt < 3; kt++) {
                uint32_t bf[2];
                LDSM_X2(bf[0], bf[1], itB + kt * 32);
                #pragma unroll
                for (int mt = 0; mt < 3; mt++) {
                    uint32_t af[4];
                    LDSM_X4(af[0], af[1], af[2], af[3],
                            aATh + mt * 16 * (ITH * 2) + kt * 32);
                    MMA_F16(wca[mt], af, bf);
                }
            }
        }
        // sim -> fp16 A tile (buffer aC) via stmatrix
        {
            const uint32_t stBase = sb + aC * 4;
            #pragma unroll
            for (int mt = 0; mt < 2; mt++) {
                float v0 = fmaf(wca[mt][0], invq[2 * mt],     -capr[2 * mt].x);
                float v1 = fmaf(wca[mt][1], invq[2 * mt],     -capr[2 * mt].y);
                float v2 = fmaf(wca[mt][2], invq[2 * mt + 1], -capr[2 * mt + 1].x);
                float v3 = fmaf(wca[mt][3], invq[2 * mt + 1], -capr[2 * mt + 1].y);
                STSM_X2(stBase + stAOff + mt * 16 * (ATH * 2),
                        h2u(v0 * v0, v1 * v1), h2u(v2 * v2, v3 * v3));
            }
            float v0 = fmaf(wca[2][0], invq[4], -capr[4].x);
            float v1 = fmaf(wca[2][1], invq[4], -capr[4].y);
            STSM_X1(stBase + stA2Off, h2u(v0 * v0, v1 * v1));
        }
        __syncthreads();   // the ONLY block sync: sim tile handoff

        // GEMM: warp w -> n slice [32w, 32w+32), k = 64
        {
            const uint32_t aBufA = sb + aC * 4 + aAOff;
            const uint32_t wtB   = sb + wtC * 4 + aWTb;
            #pragma unroll
            for (int ks = 0; ks < 4; ks++) {
                uint32_t af[3][4];
                #pragma unroll
                for (int mt = 0; mt < 3; mt++)
                    LDSM_X4(af[mt][0], af[mt][1], af[mt][2], af[mt][3],
                            aBufA + mt * 16 * (ATH * 2) + ks * 32);
                uint32_t bf[4][2];
                #pragma unroll
                for (int jb = 0; jb < 4; jb += 2) {
                    uint32_t b0, b1, b2, b3;
                    LDSM_X4(b0, b1, b2, b3,
                            wtB + jb * 8 * (WTH * 2) + ks * 32);
                    bf[jb][0] = b0; bf[jb][1] = b1;
                    bf[jb + 1][0] = b2; bf[jb + 1][1] = b3;
                }
                #pragma unroll
                for (int mt = 0; mt < 3; mt++)
                    #pragma unroll
                    for (int j = 0; j < 4; j++)
                        MMA_F16(acc[mt][j], af[mt], bf[j]);
            }
        }
    }

    // ======== Epilogue: +b, relu, per-row ssq (quad shfl), norm, store ====
    __syncthreads();
    float* sRed = sm + OFF_RED;
    #pragma unroll
    for (int mt = 0; mt < 3; mt++) {
        #pragma unroll
        for (int half = 0; half < 2; half++) {
            const int l = mt * 16 + gq + 8 * half;
            float ssq = 0.f;
            #pragma unroll
            for (int j = 0; j < 4; j++) {
                const int s = 32 * w + 8 * j + 2 * tg;
                float x0 = fmaxf(acc[mt][j][2 * half]     + sm[OFF_B + s],     0.f);
                float x1 = fmaxf(acc[mt][j][2 * half + 1] + sm[OFF_B + s + 1], 0.f);
                acc[mt][j][2 * half]     = x0;
                acc[mt][j][2 * half + 1] = x1;
                ssq = fmaf(x0, x0, ssq);
                ssq = fmaf(x1, x1, ssq);
            }
            ssq += __shfl_xor_sync(0xffffffffu, ssq, 1);
            ssq += __shfl_xor_sync(0xffffffffu, ssq, 2);
            if (tg == 0 && l < 48) sRed[l * 8 + w] = ssq;
        }
    }
    __syncthreads();
    const int clen = lens_g[c];
    if (tid < LN) {
        float ss = 0.f;
        #pragma unroll
        for (int q = 0; q < 8; q++) ss += sRed[tid * 8 + q];
        float inv = 1.f / (sqrtf(ss) + 1e-8f);
        sInv[tid] = (tid < clen) ? inv : 0.f;
    }
    __syncthreads();

    float* outB = out_g + (size_t)(c * IN_N + i) * (LN * SN);
    #pragma unroll
    for (int mt = 0; mt < 3; mt++) {
        #pragma unroll
        for (int half = 0; half < 2; half++) {
            const int l = mt * 16 + gq + 8 * half;
            if (l < LN) {
                float inv = sInv[l];
                #pragma unroll
                for (int j = 0; j < 4; j++) {
                    const int s = 32 * w + 8 * j + 2 * tg;
                    float2 o;
                    o.x = acc[mt][j][2 * half]     * inv;
                    o.y = acc[mt][j][2 * half + 1] * inv;
                    *(float2*)(outB + (size_t)l * SN + s) = o;
                }
            }
        }
    }
}

extern "C" void kernel_launch(void* const* d_in, const int* in_sizes, int n_in,
                              void* d_out, int out_size)
{
    const float* img  = (const float*)d_in[0];
    const float* cap  = (const float*)d_in[1];
    const int*   lens = (const int*)  d_in[2];
    const float* W    = (const float*)d_in[5];
    const float* b    = (const float*)d_in[6];
    float* out = (float*)d_out;
    (void)in_sizes; (void)n_in; (void)out_size;

    cudaFuncSetAttribute(graphembt_kernel,
                         cudaFuncAttributeMaxDynamicSharedMemorySize,
                         SMEM_FLOATS * sizeof(float));

    dim3 ggrid(IN_N, (RN * RN) / 8);
    gram_kernel<<<ggrid, 256>>>(img);
    wtrans_kernel<<<(DN * SN + 255) / 256, 256>>>(W);
    dim3 tgrid(IN_N, DN / 64);
    imgtrans_kernel<<<tgrid, 256>>>(img);
    imghl_kernel<<<(IN_N * RN * DN + 255) / 256, 256>>>(img);
    caphl_kernel<<<(CN * LN * DN + 255) / 256, 256>>>(cap);
    dim3 grid(IN_N, CN);
    graphembt_kernel<<<grid, NT, SMEM_FLOATS * sizeof(float)>>>(
        cap, lens, b, out);
}

// round 17
// speedup vs baseline: 2.5876x; 1.0743x over previous
#include <cuda_runtime.h>
#include <cuda_fp16.h>
#include <math.h>
#include <stdint.h>

typedef unsigned long long u64;

#define CN 64
#define IN_N 64
#define RN 36
#define LN 40
#define DN 1024
#define SN 256
#define NT 256

#define DC3 64
#define NCH3 (DN/DC3)      // 16 chunks (phase 3)
#define DC1 128
#define NCH1 (DN/DC1)      // 8 chunks (phase 1)
#define WTH 72             // WT tile stride (halves)
#define ATH 72             // A (sim) tile stride (halves)
#define ITH 56             // imgT tile stride (halves)
#define P1S 136            // phase-1 tile stride (halves)
#define RPAD 48

// ---- smem float offsets ----
#define OFF_WT0   0            // 256x72 halves = 9216 floats
#define OFF_WT1   9216
#define OFF_IT0   18432       // 64x56 halves = 1792 floats
#define OFF_IT1   20224
#define OFF_A0    22016       // 48x72 halves = 1728 floats
#define OFF_A1    23744
#define OFF_ATH   25472       // 48x56 halves = 1344 floats
#define OFF_INV   26816       // 48
#define OFF_RED   26864       // 48x8
#define OFF_B     27248       // 256
#define SMEM_FLOATS 27504     // 110016 B -> 2 CTAs/SM
// phase-1/2 unions (time-disjoint):
#define P1B       5984        // buffer stride (floats)
#define P1_IH     0           // imgH 36(+12 garbage)x136h = 3264 f
#define P1_CH     3264        // capH 40x136h = 2720 f
#define OFF_ATTN  18432       // 36x41 (past partials 0..15368)
#define OFF_GRAM  22016       // 36x37 in A0 region
#define OFF_AT    23348       // 40x40 fp32, ends 24948 < OFF_ATH

__device__ float  g_gram[IN_N * RN * RN];
__device__ __half g_WT[SN * DN];
__device__ __half g_imgT[IN_N * DN * RPAD];
__device__ __half g_imgH[IN_N * RN * DN];
__device__ __half g_capH[CN * LN * DN];

// ---------------- PTX helpers ----------------
#define MMA_F16(d, a, b) \
    asm volatile("mma.sync.aligned.m16n8k16.row.col.f32.f16.f16.f32 " \
        "{%0,%1,%2,%3}, {%4,%5,%6,%7}, {%8,%9}, {%0,%1,%2,%3};" \
        : "+f"((d)[0]), "+f"((d)[1]), "+f"((d)[2]), "+f"((d)[3]) \
        : "r"((a)[0]), "r"((a)[1]), "r"((a)[2]), "r"((a)[3]), \
          "r"((b)[0]), "r"((b)[1]))
#define CP16(saddr, gptr) \
    asm volatile("cp.async.cg.shared.global [%0], [%1], 16;" \
                 :: "r"(saddr), "l"(gptr) : "memory")
#define CP_COMMIT() asm volatile("cp.async.commit_group;" ::: "memory")
#define CP_WAIT0()  asm volatile("cp.async.wait_group 0;" ::: "memory")
#define CP_WAIT1()  asm volatile("cp.async.wait_group 1;" ::: "memory")
#define LDSM_X4(R0, R1, R2, R3, ADDR) \
    asm volatile("ldmatrix.sync.aligned.m8n8.x4.shared.b16 {%0,%1,%2,%3}, [%4];" \
        : "=r"(R0), "=r"(R1), "=r"(R2), "=r"(R3) : "r"(ADDR))
#define LDSM_X2(R0, R1, ADDR) \
    asm volatile("ldmatrix.sync.aligned.m8n8.x2.shared.b16 {%0,%1}, [%2];" \
        : "=r"(R0), "=r"(R1) : "r"(ADDR))
#define STSM_X2(ADDR, R0, R1) \
    asm volatile("stmatrix.sync.aligned.m8n8.x2.shared.b16 [%0], {%1,%2};" \
        :: "r"(ADDR), "r"(R0), "r"(R1) : "memory")
#define STSM_X1(ADDR, R0) \
    asm volatile("stmatrix.sync.aligned.m8n8.x1.shared.b16 [%0], {%1};" \
        :: "r"(ADDR), "r"(R0) : "memory")

__device__ __forceinline__ uint32_t smem_u32(const void* p) {
    uint32_t a;
    asm("{ .reg .u64 t; cvta.to.shared.u64 t, %1; cvt.u32.u64 %0, t; }"
        : "=r"(a) : "l"(p));
    return a;
}
__device__ __forceinline__ float warp_sum(float v) {
    #pragma unroll
    for (int o = 16; o > 0; o >>= 1) v += __shfl_xor_sync(0xffffffffu, v, o);
    return v;
}
__device__ __forceinline__ uint32_t h2u(float a, float b) {
    __half2 h = __floats2half2_rn(a, b);
    return *(uint32_t*)&h;
}

// ---- one-time prep kernels ----
__global__ __launch_bounds__(256)
void gram_kernel(const float* __restrict__ img_g)
{
    const int i    = blockIdx.x;
    const int widx = blockIdx.y * 8 + (threadIdx.x >> 5);
    const int lane = threadIdx.x & 31;
    const int r  = widx / RN;
    const int r2 = widx - r * RN;
    const float* A = img_g + ((size_t)i * RN + r ) * DN;
    const float* B = img_g + ((size_t)i * RN + r2) * DN;
    float s = 0.f;
    #pragma unroll 8
    for (int q = lane; q < DN; q += 32)
        s = fmaf(__ldg(A + q), __ldg(B + q), s);
    s = warp_sum(s);
    if (lane == 0) g_gram[i * RN * RN + widx] = s;
}

__global__ __launch_bounds__(256)
void wtrans_kernel(const float* __restrict__ W)
{
    int idx = blockIdx.x * 256 + threadIdx.x;
    if (idx < DN * SN) {
        int d = idx >> 8, s = idx & 255;
        g_WT[s * DN + d] = __float2half(W[idx]);
    }
}

__global__ __launch_bounds__(256)
void imgtrans_kernel(const float* __restrict__ img_g)
{
    __shared__ float t[64 * 37];
    const int i  = blockIdx.x;
    const int db = blockIdx.y;
    for (int idx = threadIdx.x; idx < RN * 64; idx += 256) {
        int r = idx >> 6, dd = idx & 63;
        t[dd * 37 + r] = img_g[((size_t)i * RN + r) * DN + db * 64 + dd];
    }
    __syncthreads();
    __half* out = g_imgT + ((size_t)i * DN + db * 64) * RPAD;
    for (int idx = threadIdx.x; idx < 64 * (RPAD / 2); idx += 256) {
        int dd = idx / (RPAD / 2), rq = idx - dd * (RPAD / 2);
        int r = 2 * rq;
        float v0 = (r     < RN) ? t[dd * 37 + r]     : 0.f;
        float v1 = (r + 1 < RN) ? t[dd * 37 + r + 1] : 0.f;
        *(__half2*)(out + dd * RPAD + r) = __floats2half2_rn(v0, v1);
    }
}

__global__ __launch_bounds__(256)
void imgh_kernel(const float* __restrict__ img_g)
{
    size_t idx = (size_t)blockIdx.x * 256 + threadIdx.x;
    if (idx < (size_t)IN_N * RN * (DN / 2)) {
        float2 v = *(const float2*)(img_g + idx * 2);
        *(__half2*)(g_imgH + idx * 2) = __floats2half2_rn(v.x, v.y);
    }
}

__global__ __launch_bounds__(256)
void caph_kernel(const float* __restrict__ cap_g)
{
    size_t idx = (size_t)blockIdx.x * 256 + threadIdx.x;
    if (idx < (size_t)CN * LN * (DN / 2)) {
        float2 v = *(const float2*)(cap_g + idx * 2);
        *(__half2*)(g_capH + idx * 2) = __floats2half2_rn(v.x, v.y);
    }
}

// ---------------- main fused kernel ----------------
__global__ __launch_bounds__(NT, 2)
void graphembt_kernel(const float* __restrict__ cap_g,
                      const int*   __restrict__ lens_g,
                      const float* __restrict__ b_g,
                      float*       __restrict__ out_g)
{
    extern __shared__ float sm[];
    const int i    = blockIdx.x;
    const int c    = blockIdx.y;
    const int tid  = threadIdx.x;
    const int w    = tid >> 5;       // 0..7
    const int lane = tid & 31;
    const int gq   = lane >> 2;
    const int tg   = lane & 3;
    const int l15  = lane & 15;
    const int l7   = lane & 7;
    const int khA  = lane >> 4;
    const int khB  = (lane >> 3) & 1;
    const int jm   = (lane >> 4) & 1;

    const uint32_t sb = smem_u32(sm);
    const float* capB = cap_g + (size_t)c * (LN * DN);

    if (tid < SN / 4)
        *(float4*)(sm + OFF_B + tid * 4) = *(const float4*)(b_g + tid * 4);

    // ======== Phase 1: attn via single fp16 MMA product ========
    const __half* iH = g_imgH + (size_t)i * RN * DN;
    const __half* cH = g_capH + (size_t)c * LN * DN;

    float accA[15][4];
    #pragma unroll
    for (int t = 0; t < 15; t++)
        #pragma unroll
        for (int q = 0; q < 4; q++) accA[t][q] = 0.f;

    const uint32_t aOffA  = l15 * (P1S * 2) + khA * 16;
    const uint32_t bOffX4 = (8 * jm + l7) * (P1S * 2) + khB * 16;
    const uint32_t bOffX2 = (32 + l7) * (P1S * 2) + khB * 16;

    // prologue: stage chunk 0 into buf0 (128 d)
    {
        for (int idx = tid; idx < 576; idx += NT) {
            int r = idx >> 4, q = idx & 15;
            CP16(sb + (P1_IH) * 4 + r * (P1S * 2) + q * 16,
                 (const char*)(iH + (size_t)r * DN) + q * 16);
        }
        for (int idx = tid; idx < 640; idx += NT) {
            int l = idx >> 4, q = idx & 15;
            CP16(sb + (P1_CH) * 4 + l * (P1S * 2) + q * 16,
                 (const char*)(cH + (size_t)l * DN) + q * 16);
        }
        CP_COMMIT();
    }

    for (int ch = 0; ch < NCH1; ch++) {
        const int B0 = (ch & 1) ? P1B : 0;
        CP_WAIT0();
        __syncthreads();
        if (ch + 1 < NCH1) {
            const int BN = (ch & 1) ? 0 : P1B;
            const int dof = (ch + 1) * DC1;
            for (int idx = tid; idx < 576; idx += NT) {
                int r = idx >> 4, q = idx & 15;
                CP16(sb + (BN + P1_IH) * 4 + r * (P1S * 2) + q * 16,
                     (const char*)(iH + (size_t)r * DN + dof) + q * 16);
            }
            for (int idx = tid; idx < 640; idx += NT) {
                int l = idx >> 4, q = idx & 15;
                CP16(sb + (BN + P1_CH) * 4 + l * (P1S * 2) + q * 16,
                     (const char*)(cH + (size_t)l * DN + dof) + q * 16);
            }
            CP_COMMIT();
        }

        // warp w handles k-slice ks=w
        {
            const uint32_t kOff = w * 32;
            const uint32_t aH = sb + (B0 + P1_IH) * 4 + aOffA + kOff;
            const uint32_t bH = sb + (B0 + P1_CH) * 4 + kOff;

            uint32_t afH[3][4];
            #pragma unroll
            for (int mt = 0; mt < 3; mt++)
                LDSM_X4(afH[mt][0], afH[mt][1], afH[mt][2], afH[mt][3],
                        aH + mt * 16 * (P1S * 2));
            uint32_t bfH[5][2];
            #pragma unroll
            for (int jb = 0; jb < 4; jb += 2) {
                uint32_t b0, b1, b2, b3;
                LDSM_X4(b0, b1, b2, b3, bH + bOffX4 + jb * 8 * (P1S * 2));
                bfH[jb][0] = b0; bfH[jb][1] = b1;
                bfH[jb + 1][0] = b2; bfH[jb + 1][1] = b3;
            }
            LDSM_X2(bfH[4][0], bfH[4][1], bH + bOffX2);

            #pragma unroll
            for (int mt = 0; mt < 3; mt++)
                #pragma unroll
                for (int nt = 0; nt < 5; nt++)
                    MMA_F16(accA[mt * 5 + nt], afH[mt], bfH[nt]);
        }
    }
    __syncthreads();   // phase-1 tiles dead; reuse region for partials

    {
        float* sPart = sm + (size_t)w * 1921;
        #pragma unroll
        for (int mt = 0; mt < 3; mt++)
            #pragma unroll
            for (int nt = 0; nt < 5; nt++) {
                const int rr = mt * 16 + gq;
                const int cc = nt * 8 + 2 * tg;
                sPart[rr * 40 + cc]           = accA[mt * 5 + nt][0];
                sPart[rr * 40 + cc + 1]       = accA[mt * 5 + nt][1];
                sPart[(rr + 8) * 40 + cc]     = accA[mt * 5 + nt][2];
                sPart[(rr + 8) * 40 + cc + 1] = accA[mt * 5 + nt][3];
            }
    }
    __syncthreads();
    float* sAttn = sm + OFF_ATTN;
    for (int idx = tid; idx < RN * 40; idx += NT) {
        int r = idx / 40, l = idx - r * 40;
        float s = 0.f;
        #pragma unroll
        for (int q = 0; q < 8; q++) s += sm[q * 1921 + r * 40 + l];
        sAttn[r * 41 + l] = s;
    }
    __syncthreads();

    // ======== Phase 2a: leaky+l2norm(l); stage Gram concurrently ========
    float* sGrm = sm + OFF_GRAM;
    if (tid < RN) {
        float ss = 0.f;
        #pragma unroll 4
        for (int l = 0; l < LN; l++) {
            float x = sAttn[tid * 41 + l];
            x = (x > 0.f) ? x : 0.1f * x;
            sAttn[tid * 41 + l] = x;
            ss = fmaf(x, x, ss);
        }
        float inv = 1.f / (sqrtf(ss) + 1e-8f);
        #pragma unroll 4
        for (int l = 0; l < LN; l++) sAttn[tid * 41 + l] *= inv;
    }
    for (int idx = tid; idx < RN * RN; idx += NT) {
        int r = idx / RN, r2 = idx - (idx / RN) * RN;
        sGrm[r * 37 + r2] = g_gram[i * RN * RN + idx];
    }
    __syncthreads();

    // ======== Phase 2b: softmax over r -> sAT[l][r] (fp32) ========
    float* sAT = sm + OFF_AT;
    if (tid < LN) {
        float mx = -1e30f;
        #pragma unroll 4
        for (int r = 0; r < RN; r++)
            mx = fmaxf(mx, sAttn[r * 41 + tid] * 9.0f);
        float ev[RN];
        float sum = 0.f;
        #pragma unroll 4
        for (int r = 0; r < RN; r++) {
            float e = expf(sAttn[r * 41 + tid] * 9.0f - mx);
            ev[r] = e;
            sum += e;
        }
        float inv = 1.f / sum;
        #pragma unroll 4
        for (int r = 0; r < RN; r++) sAT[tid * 40 + r] = ev[r] * inv;
    }
    __syncthreads();

    // ======== ssq via Gram + build fp16 sATh ========
    float* sInv = sm + OFF_INV;
    #pragma unroll
    for (int q = 0; q < 5; q++) {
        const int l = w + 8 * q;
        float t = 0.f, t2 = 0.f;
        #pragma unroll 4
        for (int rp = 0; rp < RN; rp++) {
            float a = sAT[l * 40 + rp];
            t = fmaf(sGrm[lane * 37 + rp], a, t);
            if (lane < 4)
                t2 = fmaf(sGrm[(32 + lane) * 37 + rp], a, t2);
        }
        float part = sAT[l * 40 + lane] * t;
        if (lane < 4) part += sAT[l * 40 + 32 + lane] * t2;
        float ss = warp_sum(part);
        if (lane == 0) sInv[l] = 1.f / (sqrtf(ss) + 1e-8f);
    }
    {
        __half* sATh = (__half*)(sm + OFF_ATH);
        for (int idx = tid; idx < 48 * (ITH / 2); idx += NT) {
            int l = idx / (ITH / 2), rq = idx - l * (ITH / 2);
            int r = 2 * rq;
            float v0 = (l < LN && r     < RN) ? sAT[l * 40 + r]     : 0.f;
            float v1 = (l < LN && r + 1 < RN) ? sAT[l * 40 + r + 1] : 0.f;
            *(__half2*)(sATh + l * ITH + r) = __floats2half2_rn(v0, v1);
        }
    }
    __syncthreads();   // sGrm/sAT consumed -> A-tile region free

    // zero both A tiles (rows 40..47 must stay zero)
    for (int idx = tid; idx < 864; idx += NT) {
        float4 z = make_float4(0.f, 0.f, 0.f, 0.f);
        *(float4*)(sm + OFF_A0 + idx * 4) = z;
    }
    float invq[5];
    #pragma unroll
    for (int q = 0; q < 5; q++) invq[q] = sInv[gq + 8 * q];
    __syncthreads();   // A tiles zeroed before any warp's stmatrix/ldmatrix

    // per-warp staging bases
    const __half* gWTw = g_WT + (size_t)(32 * w) * DN;
    const __half* gITw = g_imgT + ((size_t)i * DN + 8 * w) * RPAD;

    // prologue: per-warp stage chunk 0
    {
        for (int t = lane; t < 256; t += 32) {
            int sl = t >> 3, q = t & 7;
            CP16(sb + OFF_WT0 * 4 + (32 * w + sl) * (WTH * 2) + q * 16,
                 (const char*)(gWTw + (size_t)sl * DN) + q * 16);
        }
        for (int t = lane; t < 48; t += 32) {
            int dl = t / 6, q = t - dl * 6;
            CP16(sb + OFF_IT0 * 4 + (8 * w + dl) * (ITH * 2) + q * 16,
                 (const char*)(gITw + (size_t)dl * RPAD) + q * 16);
        }
        CP_COMMIT();
    }

    // ldmatrix/stmatrix lane offsets
    const uint32_t aAOff = l15 * (ATH * 2) + khA * 16;
    const uint32_t aATh  = sb + OFF_ATH * 4 + l15 * (ITH * 2) + khA * 16;
    const uint32_t aITb  = (8 * w + l7) * (ITH * 2) + khB * 16;
    const uint32_t aWTb  = (32 * w + 8 * jm + l7) * (WTH * 2) + khB * 16;
    const uint32_t stAOff  = l15 * (ATH * 2) + w * 16;
    const uint32_t stA2Off = (32 + l7) * (ATH * 2) + w * 16;

    // ======== Phase 3: per-warp staged, 1 sync/chunk ========
    float acc[3][4][4];
    #pragma unroll
    for (int mt = 0; mt < 3; mt++)
        #pragma unroll
        for (int j = 0; j < 4; j++)
            #pragma unroll
            for (int q = 0; q < 4; q++) acc[mt][j][q] = 0.f;

    for (int ch = 0; ch < NCH3; ch++) {
        const int cur = ch & 1;
        const int wtC = cur ? OFF_WT1 : OFF_WT0;
        const int itC = cur ? OFF_IT1 : OFF_IT0;
        const int aC  = cur ? OFF_A1  : OFF_A0;

        if (ch + 1 < NCH3) {
            const int wtN = cur ? OFF_WT0 : OFF_WT1;
            const int itN = cur ? OFF_IT0 : OFF_IT1;
            const int dof = (ch + 1) * DC3;
            for (int t = lane; t < 256; t += 32) {
                int sl = t >> 3, q = t & 7;
                CP16(sb + wtN * 4 + (32 * w + sl) * (WTH * 2) + q * 16,
                     (const char*)(gWTw + (size_t)sl * DN + dof) + q * 16);
            }
            for (int t = lane; t < 48; t += 32) {
                int dl = t / 6, q = t - dl * 6;
                CP16(sb + itN * 4 + (8 * w + dl) * (ITH * 2) + q * 16,
                     (const char*)(gITw + (size_t)(dof + dl) * RPAD) + q * 16);
            }
            CP_COMMIT();
            CP_WAIT1();
        } else {
            CP_WAIT0();
        }
        __syncwarp();

        float2 capr[5];
        {
            const float* cp = capB + ch * DC3 + 8 * w + 2 * tg;
            #pragma unroll
            for (int q = 0; q < 5; q++)
                capr[q] = *(const float2*)(cp + (size_t)(gq + 8 * q) * DN);
        }

        // wc via mma: warp w -> d in [8w, 8w+8)
        float wca[3][4];
        #pragma unroll
        for (int mt = 0; mt < 3; mt++)
            #pragma unroll
            for (int q = 0; q < 4; q++) wca[mt][q] = 0.f;
        {
            const uint32_t itB = sb + itC * 4 + aITb;
            #pragma unroll
            for (int kt = 0; kt < 3; kt++) {
                uint32_t bf[2];
                LDSM_X2(bf[0], bf[1], itB + kt * 32);
                #pragma unroll
                for (int mt = 0; mt < 3; mt++) {
                    uint32_t af[4];
                    LDSM_X4(af[0], af[1], af[2], af[3],
                            aATh + mt * 16 * (ITH * 2) + kt * 32);
                    MMA_F16(wca[mt], af, bf);
                }
            }
        }
        // sim -> fp16 A tile (buffer aC) via stmatrix
        {
            const uint32_t stBase = sb + aC * 4;
            #pragma unroll
            for (int mt = 0; mt < 2; mt++) {
                float v0 = fmaf(wca[mt][0], invq[2 * mt],     -capr[2 * mt].x);
                float v1 = fmaf(wca[mt][1], invq[2 * mt],     -capr[2 * mt].y);
                float v2 = fmaf(wca[mt][2], invq[2 * mt + 1], -capr[2 * mt + 1].x);
                float v3 = fmaf(wca[mt][3], invq[2 * mt + 1], -capr[2 * mt + 1].y);
                STSM_X2(stBase + stAOff + mt * 16 * (ATH * 2),
                        h2u(v0 * v0, v1 * v1), h2u(v2 * v2, v3 * v3));
            }
            float v0 = fmaf(wca[2][0], invq[4], -capr[4].x);
            float v1 = fmaf(wca[2][1], invq[4], -capr[4].y);
            STSM_X1(stBase + stA2Off, h2u(v0 * v0, v1 * v1));
        }
        __syncthreads();   // sim tile handoff

        // GEMM: warp w -> n slice [32w, 32w+32), k = 64
        {
            const uint32_t aBufA = sb + aC * 4 + aAOff;
            const uint32_t wtB   = sb + wtC * 4 + aWTb;
            #pragma unroll
            for (int ks = 0; ks < 4; ks++) {
                uint32_t af[3][4];
                #pragma unroll
                for (int mt = 0; mt < 3; mt++)
                    LDSM_X4(af[mt][0], af[mt][1], af[mt][2], af[mt][3],
                            aBufA + mt * 16 * (ATH * 2) + ks * 32);
                uint32_t bf[4][2];
                #pragma unroll
                for (int jb = 0; jb < 4; jb += 2) {
                    uint32_t b0, b1, b2, b3;
                    LDSM_X4(b0, b1, b2, b3,
                            wtB + jb * 8 * (WTH * 2) + ks * 32);
                    bf[jb][0] = b0; bf[jb][1] = b1;
                    bf[jb + 1][0] = b2; bf[jb + 1][1] = b3;
                }
                #pragma unroll
                for (int mt = 0; mt < 3; mt++)
                    #pragma unroll
                    for (int j = 0; j < 4; j++)
                        MMA_F16(acc[mt][j], af[mt], bf[j]);
            }
        }
    }

    // ======== Epilogue: +b, relu, per-row ssq (quad shfl), norm, store ====
    __syncthreads();
    float* sRed = sm + OFF_RED;
    #pragma unroll
    for (int mt = 0; mt < 3; mt++) {
        #pragma unroll
        for (int half = 0; half < 2; half++) {
            const int l = mt * 16 + gq + 8 * half;
            float ssq = 0.f;
            #pragma unroll
            for (int j = 0; j < 4; j++) {
                const int s = 32 * w + 8 * j + 2 * tg;
                float x0 = fmaxf(acc[mt][j][2 * half]     + sm[OFF_B + s],     0.f);
                float x1 = fmaxf(acc[mt][j][2 * half + 1] + sm[OFF_B + s + 1], 0.f);
                acc[mt][j][2 * half]     = x0;
                acc[mt][j][2 * half + 1] = x1;
                ssq = fmaf(x0, x0, ssq);
                ssq = fmaf(x1, x1, ssq);
            }
            ssq += __shfl_xor_sync(0xffffffffu, ssq, 1);
            ssq += __shfl_xor_sync(0xffffffffu, ssq, 2);
            if (tg == 0 && l < 48) sRed[l * 8 + w] = ssq;
        }
    }
    __syncthreads();
    const int clen = lens_g[c];
    if (tid < LN) {
        float ss = 0.f;
        #pragma unroll
        for (int q = 0; q < 8; q++) ss += sRed[tid * 8 + q];
        float inv = 1.f / (sqrtf(ss) + 1e-8f);
        sInv[tid] = (tid < clen) ? inv : 0.f;
    }
    __syncthreads();

    float* outB = out_g + (size_t)(c * IN_N + i) * (LN * SN);
    #pragma unroll
    for (int mt = 0; mt < 3; mt++) {
        #pragma unroll
        for (int half = 0; half < 2; half++) {
            const int l = mt * 16 + gq + 8 * half;
            if (l < LN) {
                float inv = sInv[l];
                #pragma unroll
                for (int j = 0; j < 4; j++) {
                    const int s = 32 * w + 8 * j + 2 * tg;
                    float2 o;
                    o.x = acc[mt][j][2 * half]     * inv;
                    o.y = acc[mt][j][2 * half + 1] * inv;
                    *(float2*)(outB + (size_t)l * SN + s) = o;
                }
            }
        }
    }
}

extern "C" void kernel_launch(void* const* d_in, const int* in_sizes, int n_in,
                              void* d_out, int out_size)
{
    const float* img  = (const float*)d_in[0];
    const float* cap  = (const float*)d_in[1];
    const int*   lens = (const int*)  d_in[2];
    const float* W    = (const float*)d_in[5];
    const float* b    = (const float*)d_in[6];
    float* out = (float*)d_out;
    (void)in_sizes; (void)n_in; (void)out_size;

    cudaFuncSetAttribute(graphembt_kernel,
                         cudaFuncAttributeMaxDynamicSharedMemorySize,
                         SMEM_FLOATS * sizeof(float));

    dim3 ggrid(IN_N, (RN * RN) / 8);
    gram_kernel<<<ggrid, 256>>>(img);
    wtrans_kernel<<<(DN * SN + 255) / 256, 256>>>(W);
    dim3 tgrid(IN_N, DN / 64);
    imgtrans_kernel<<<tgrid, 256>>>(img);
    imgh_kernel<<<(IN_N * RN * DN / 2 + 255) / 256, 256>>>(img);
    caph_kernel<<<(CN * LN * DN / 2 + 255) / 256, 256>>>(cap);
    dim3 grid(IN_N, CN);
    graphembt_kernel<<<grid, NT, SMEM_FLOATS * sizeof(float)>>>(
        cap, lens, b, out);
}